// round 2
// baseline (speedup 1.0000x reference)
#include <cuda_runtime.h>
#include <cuda_bf16.h>
#include <math.h>

// Problem constants (fixed by reference: B=4, N=1024, C=768, H=12, Dh=64)
#define PB 4
#define PN 1024
#define PC 768
#define PH 12
#define PD 64
#define PSCALE 0.125f   // 64^-0.5

// ---------------- scratch (static device arrays; no allocation) ----------------
__device__ float g_qkv[(long)PB * PN * 3 * PC];          // 36 MB  [B,N,3,H,D]
__device__ float g_q[(long)PB * PH * PN * PD];           // 12 MB  [B,H,N,D]
__device__ float g_k[(long)PB * PH * PN * PD];
__device__ float g_v[(long)PB * PH * PN * PD];
__device__ float g_s[(long)PB * PH * PN * PN];           // 192 MB [B,H,N,N]
__device__ float g_o[(long)PB * PN * PC];                // 12 MB  [B,N,C]

// ---------------- generic tiled fp32 GEMM ----------------
// C[M,N] = A[M,K] * op(B) (+bias), A row-major lda=K.
// NT=true : B is [N,K] row-major (C = A B^T)
// NT=false: B is [K,N] row-major (C = A B)
// Batched over blockIdx.z: A += z*sA, B += z*sB, C += (z/CB)*sCb + (z%CB)*sCh.
template<int BM, int BN, int BK, int TM, int TN, bool NT>
__global__ void __launch_bounds__(256)
gemm_tpl(const float* __restrict__ Ab, const float* __restrict__ Bb,
         float* __restrict__ Cb, const float* __restrict__ bias,
         int M, int N, int K,
         long sA, long sB, long sCb, long sCh, int CB, int ldc)
{
    constexpr int THREADS = (BM / TM) * (BN / TN);
    static_assert(THREADS == 256, "expect 256 threads");

    const int z = blockIdx.z;
    const float* A = Ab + (long)z * sA;
    const float* B = Bb + (long)z * sB;
    float* C = Cb + (long)(z / CB) * sCb + (long)(z % CB) * sCh;

    __shared__ float As[BK][BM + 1];
    __shared__ float Bs[BK][BN + (NT ? 1 : 0)];

    const int tid = threadIdx.x;
    const int m0 = blockIdx.y * BM;
    const int n0 = blockIdx.x * BN;

    const int tx = tid % (BN / TN);
    const int ty = tid / (BN / TN);

    float acc[TM][TN];
    #pragma unroll
    for (int i = 0; i < TM; i++)
        #pragma unroll
        for (int j = 0; j < TN; j++) acc[i][j] = 0.0f;

    for (int k0 = 0; k0 < K; k0 += BK) {
        // ---- load A tile (k-contiguous, float4 along k, store transposed) ----
        {
            constexpr int TPR = BK / 4;             // threads per row
            constexpr int RPP = THREADS / TPR;      // rows per pass
            const int r  = tid / TPR;
            const int kc = (tid % TPR) * 4;
            #pragma unroll
            for (int rr = 0; rr < BM; rr += RPP) {
                float4 vv = *(const float4*)(A + (long)(m0 + r + rr) * K + k0 + kc);
                As[kc + 0][r + rr] = vv.x;
                As[kc + 1][r + rr] = vv.y;
                As[kc + 2][r + rr] = vv.z;
                As[kc + 3][r + rr] = vv.w;
            }
        }
        // ---- load B tile ----
        if constexpr (NT) {
            constexpr int TPR = BK / 4;
            constexpr int RPP = THREADS / TPR;
            const int r  = tid / TPR;
            const int kc = (tid % TPR) * 4;
            #pragma unroll
            for (int rr = 0; rr < BN; rr += RPP) {
                float4 vv = *(const float4*)(B + (long)(n0 + r + rr) * K + k0 + kc);
                Bs[kc + 0][r + rr] = vv.x;
                Bs[kc + 1][r + rr] = vv.y;
                Bs[kc + 2][r + rr] = vv.z;
                Bs[kc + 3][r + rr] = vv.w;
            }
        } else {
            constexpr int TPK = BN / 4;             // threads per k-row
            constexpr int KPP = THREADS / TPK;      // k-rows per pass
            const int kr = tid / TPK;
            const int nc = (tid % TPK) * 4;
            #pragma unroll
            for (int kk = 0; kk < BK; kk += KPP) {
                float4 vv = *(const float4*)(B + (long)(k0 + kr + kk) * N + n0 + nc);
                *(float4*)&Bs[kr + kk][nc] = vv;
            }
        }
        __syncthreads();

        #pragma unroll
        for (int k = 0; k < BK; k++) {
            float a[TM], b[TN];
            #pragma unroll
            for (int i = 0; i < TM; i++) a[i] = As[k][ty * TM + i];
            #pragma unroll
            for (int j = 0; j < TN; j++) b[j] = Bs[k][tx * TN + j];
            #pragma unroll
            for (int i = 0; i < TM; i++)
                #pragma unroll
                for (int j = 0; j < TN; j++)
                    acc[i][j] += a[i] * b[j];
        }
        __syncthreads();
    }

    #pragma unroll
    for (int i = 0; i < TM; i++) {
        const int gi = m0 + ty * TM + i;
        #pragma unroll
        for (int j = 0; j < TN; j++) {
            const int gj = n0 + tx * TN + j;
            float v = acc[i][j];
            if (bias) v += bias[gj];
            C[(long)gi * ldc + gj] = v;
        }
    }
}

// ---------------- pack qkv [B,N,3,H,D] -> q,k,v [B,H,N,D], scale q ----------------
__global__ void __launch_bounds__(256)
pack_qkv(const float* __restrict__ qkv,
         float* __restrict__ q, float* __restrict__ k,
         float* __restrict__ v)
{
    const long idx = (long)blockIdx.x * blockDim.x + threadIdx.x;     // float4 index
    const long total4 = (long)PB * PN * 3 * PC / 4;
    if (idx >= total4) return;
    const long e = idx * 4;
    const int bn = (int)(e / (3 * PC));
    const int r  = (int)(e % (3 * PC));
    const int s  = r / PC;
    const int r2 = r % PC;
    const int h  = r2 / PD;
    const int d  = r2 % PD;
    const int b  = bn / PN;
    const int n  = bn % PN;

    float4 val = *(const float4*)(qkv + e);
    const long dst = (((long)(b * PH + h) * PN) + n) * PD + d;
    if (s == 0) {
        val.x *= PSCALE; val.y *= PSCALE; val.z *= PSCALE; val.w *= PSCALE;
        *(float4*)(q + dst) = val;
    } else if (s == 1) {
        *(float4*)(k + dst) = val;
    } else {
        *(float4*)(v + dst) = val;
    }
}

// ---------------- fused talking-heads pre-mix + softmax + post-mix + attnscale ----------------
// One block per (b, n) row. In-place on g_s. 384 threads = 12 warps (1 warp/head for softmax).
__global__ void __launch_bounds__(384)
talking_softmax(float* __restrict__ S,
                const float* __restrict__ W_l, const float* __restrict__ b_l,
                const float* __restrict__ W_w, const float* __restrict__ b_w,
                const float* __restrict__ lamb)
{
    extern __shared__ float sraw[];
    float (*sbuf)[PN] = (float(*)[PN])sraw;          // [12][1024] = 48 KB

    __shared__ float wl[PH * PH], ww[PH * PH];
    __shared__ float bl[PH], bw[PH], lam[PH];

    const int tid = threadIdx.x;                      // 0..383
    const int row = blockIdx.x;
    const int b = row >> 10;
    const int n = row & 1023;

    if (tid < PH * PH) { wl[tid] = W_l[tid]; ww[tid] = W_w[tid]; }
    if (tid < PH)      { bl[tid] = b_l[tid]; bw[tid] = b_w[tid]; lam[tid] = lamb[tid]; }

    // load all 12 head-rows for (b,n): 12*256 float4s across 384 threads
    for (int t = tid; t < PH * (PN / 4); t += 384) {
        const int h  = t >> 8;
        const int m4 = t & 255;
        const long base = (((long)(b * PH + h) * PN) + n) * PN;
        *(float4*)&sbuf[h][m4 * 4] = *(const float4*)(S + base + m4 * 4);
    }
    __syncthreads();

    // pre-softmax talking heads: t[g] = sum_h W_l[g,h] * s[h] + b_l[g]   (in-place per column)
    for (int m = tid; m < PN; m += 384) {
        float s[PH], o[PH];
        #pragma unroll
        for (int h = 0; h < PH; h++) s[h] = sbuf[h][m];
        #pragma unroll
        for (int g = 0; g < PH; g++) {
            float t = bl[g];
            #pragma unroll
            for (int h = 0; h < PH; h++) t += wl[g * PH + h] * s[h];
            o[g] = t;
        }
        #pragma unroll
        for (int g = 0; g < PH; g++) sbuf[g][m] = o[g];
    }
    __syncthreads();

    // softmax over m: warp w handles head w
    {
        const int w = tid >> 5;
        const int l = tid & 31;
        float mx = -INFINITY;
        for (int m = l; m < PN; m += 32) mx = fmaxf(mx, sbuf[w][m]);
        #pragma unroll
        for (int off = 16; off > 0; off >>= 1)
            mx = fmaxf(mx, __shfl_xor_sync(0xFFFFFFFFu, mx, off));
        float sum = 0.0f;
        for (int m = l; m < PN; m += 32) {
            const float e = __expf(sbuf[w][m] - mx);
            sbuf[w][m] = e;
            sum += e;
        }
        #pragma unroll
        for (int off = 16; off > 0; off >>= 1)
            sum += __shfl_xor_sync(0xFFFFFFFFu, sum, off);
        const float inv = 1.0f / sum;
        for (int m = l; m < PN; m += 32) sbuf[w][m] *= inv;
    }
    __syncthreads();

    // post-softmax talking heads + attnscale (in-place per column)
    const float attn_d = 1.0f / (float)PN;
    for (int m = tid; m < PN; m += 384) {
        float p[PH], o[PH];
        #pragma unroll
        for (int h = 0; h < PH; h++) p[h] = sbuf[h][m];
        #pragma unroll
        for (int g = 0; g < PH; g++) {
            float a = bw[g];
            #pragma unroll
            for (int h = 0; h < PH; h++) a += ww[g * PH + h] * p[h];
            // attn_d + (a - attn_d)*(1+lam) = a*(1+lam) - attn_d*lam
            o[g] = a * (1.0f + lam[g]) - attn_d * lam[g];
        }
        #pragma unroll
        for (int g = 0; g < PH; g++) sbuf[g][m] = o[g];
    }
    __syncthreads();

    // store back (in place)
    for (int t = tid; t < PH * (PN / 4); t += 384) {
        const int h  = t >> 8;
        const int m4 = t & 255;
        const long base = (((long)(b * PH + h) * PN) + n) * PN;
        *(float4*)(S + base + m4 * 4) = *(const float4*)&sbuf[h][m4 * 4];
    }
}

// ---------------- launcher ----------------
extern "C" void kernel_launch(void* const* d_in, const int* in_sizes, int n_in,
                              void* d_out, int out_size)
{
    const float* x      = (const float*)d_in[0];
    const float* W_qkv  = (const float*)d_in[1];
    const float* W_proj = (const float*)d_in[2];
    const float* b_proj = (const float*)d_in[3];
    const float* W_l    = (const float*)d_in[4];
    const float* b_l    = (const float*)d_in[5];
    const float* W_w    = (const float*)d_in[6];
    const float* b_w    = (const float*)d_in[7];
    const float* lamb   = (const float*)d_in[8];
    float* out = (float*)d_out;

    float *qkv, *q, *k, *v, *s, *o;
    cudaGetSymbolAddress((void**)&qkv, g_qkv);
    cudaGetSymbolAddress((void**)&q,   g_q);
    cudaGetSymbolAddress((void**)&k,   g_k);
    cudaGetSymbolAddress((void**)&v,   g_v);
    cudaGetSymbolAddress((void**)&s,   g_s);
    cudaGetSymbolAddress((void**)&o,   g_o);

    const int M  = PB * PN;          // 4096
    const long qkstride = (long)PN * PD;      // 65536 per (b,h)
    const long sstride  = (long)PN * PN;      // 1048576 per (b,h)

    // 1) QKV projection: [4096,768] x [2304,768]^T -> [4096,2304]
    {
        dim3 grid(3 * PC / 128, M / 128, 1);
        gemm_tpl<128, 128, 16, 8, 8, true><<<grid, 256>>>(
            x, W_qkv, qkv, nullptr, M, 3 * PC, PC,
            0, 0, 0, 0, PH, 3 * PC);
    }

    // 2) pack + scale q
    {
        const long total4 = (long)PB * PN * 3 * PC / 4;
        const int blocks = (int)((total4 + 255) / 256);
        pack_qkv<<<blocks, 256>>>(qkv, q, k, v);
    }

    // 3) scores: per (b,h): S = q k^T, [1024,1024], K=64, batched over 48
    {
        dim3 grid(PN / 128, PN / 128, PB * PH);
        gemm_tpl<128, 128, 16, 8, 8, true><<<grid, 256>>>(
            q, k, s, nullptr, PN, PN, PD,
            qkstride, qkstride, (long)PH * sstride, sstride, PH, PN);
    }

    // 4) fused talking-heads + softmax (in place on s)
    {
        static bool attr_set = false;
        if (!attr_set) {
            cudaFuncSetAttribute(talking_softmax,
                                 cudaFuncAttributeMaxDynamicSharedMemorySize, 49152);
            attr_set = true;
        }
        talking_softmax<<<PB * PN, 384, 49152>>>(s, W_l, b_l, W_w, b_w, lamb);
    }

    // 5) O = A @ V: per (b,h): [1024,1024] x [1024,64], write into [B,N,C] at col h*64
    {
        dim3 grid(PD / 64, PN / 64, PB * PH);
        gemm_tpl<64, 64, 16, 4, 4, false><<<grid, 256>>>(
            s, v, o, nullptr, PN, PD, PN,
            sstride, qkstride, (long)PN * PC, (long)PD, PH, PC);
    }

    // 6) output projection + bias: [4096,768] x [768,768]^T -> d_out
    {
        dim3 grid(PC / 128, M / 128, 1);
        gemm_tpl<128, 128, 16, 8, 8, true><<<grid, 256>>>(
            o, W_proj, out, b_proj, M, PC, PC,
            0, 0, 0, 0, PH, PC);
    }
}

// round 5
// speedup vs baseline: 1.3480x; 1.3480x over previous
#include <cuda_runtime.h>
#include <cuda_bf16.h>
#include <math.h>
#include <stdint.h>

// Problem constants (fixed by reference: B=4, N=1024, C=768, H=12, Dh=64)
#define PB 4
#define PN 1024
#define PC 768
#define PH 12
#define PD 64
#define PSCALE 0.125f   // 64^-0.5

// ---------------- scratch (static device arrays; no allocation) ----------------
__device__ float g_qkv[(long)PB * PN * 3 * PC];          // 36 MB  [B,N,3,H,D]
__device__ float g_q[(long)PB * PH * PN * PD];           // 12 MB  [B,H,N,D]
__device__ float g_k[(long)PB * PH * PN * PD];
__device__ float g_v[(long)PB * PH * PN * PD];
__device__ float g_s[(long)PB * PH * PN * PN];           // 192 MB [B,H,N,N]
__device__ float g_o[(long)PB * PN * PC];                // 12 MB  [B,N,C]

// tf32 conversion: destination of cvt.*.tf32.f32 must be a b32 register.
__device__ __forceinline__ float to_tf32(float x) {
    uint32_t r;
    asm("cvt.rna.tf32.f32 %0, %1;" : "=r"(r) : "f"(x));
    return __uint_as_float(r);
}

__device__ __forceinline__ void mma_tf32(float& c0, float& c1, float& c2, float& c3,
                                         uint32_t a0, uint32_t a1, uint32_t a2, uint32_t a3,
                                         uint32_t b0, uint32_t b1) {
    asm volatile(
        "mma.sync.aligned.m16n8k8.row.col.f32.tf32.tf32.f32 "
        "{%0,%1,%2,%3}, {%4,%5,%6,%7}, {%8,%9}, {%0,%1,%2,%3};"
        : "+f"(c0), "+f"(c1), "+f"(c2), "+f"(c3)
        : "r"(a0), "r"(a1), "r"(a2), "r"(a3), "r"(b0), "r"(b1));
}

// ---------------- tf32 tensor-core GEMM ----------------
// C[M,N] = A[M,K] * op(B) (+bias), all row-major fp32 in gmem, tf32 in mma.
// NT=true : B is [N,K] row-major (C = A B^T)
// NT=false: B is [K,N] row-major (C = A B)
// Batched over blockIdx.z: A += z*sA, B += z*sB, C += (z/CB)*sCb + (z%CB)*sCh.
template<int BM, int BN, int BK, int WM, int WN, bool NT>
__global__ void __launch_bounds__(256)
gemm_tf32(const float* __restrict__ Ab, const float* __restrict__ Bb,
          float* __restrict__ Cb, const float* __restrict__ bias,
          int M, int N, int K,
          long sA, long sB, long sCb, long sCh, int CB, int ldc)
{
    static_assert(WM * WN == 8, "8 warps");
    constexpr int BKP = BK + 4;
    constexpr int BNP = BN + 4;
    constexpr int WTM = BM / WM;       // warp tile M
    constexpr int WTN = BN / WN;       // warp tile N
    constexpr int MT  = WTM / 16;      // mma tiles per warp (M)
    constexpr int NTt = WTN / 8;       // mma tiles per warp (N)

    __shared__ float As[BM][BKP];
    __shared__ float Bs[BK][BNP];

    const int z = blockIdx.z;
    const float* A = Ab + (long)z * sA;
    const float* B = Bb + (long)z * sB;
    float* C = Cb + (long)(z / CB) * sCb + (long)(z % CB) * sCh;

    const int tid  = threadIdx.x;
    const int warp = tid >> 5;
    const int lane = tid & 31;
    const int g    = lane >> 2;        // group id 0..7
    const int c4   = lane & 3;         // 0..3
    const int wm   = warp % WM;
    const int wn   = warp / WM;

    const int m0 = blockIdx.y * BM;
    const int n0 = blockIdx.x * BN;

    float acc[MT][NTt][4];
    #pragma unroll
    for (int i = 0; i < MT; i++)
        #pragma unroll
        for (int j = 0; j < NTt; j++)
            #pragma unroll
            for (int r = 0; r < 4; r++) acc[i][j][r] = 0.0f;

    for (int k0 = 0; k0 < K; k0 += BK) {
        // ---- A tile: [BM][BK], global rows K-contiguous, float4 along K ----
        {
            constexpr int TPR = BK / 4;            // threads per row
            constexpr int RPP = 256 / TPR;         // rows per pass
            const int r  = tid / TPR;
            const int kc = (tid % TPR) * 4;
            #pragma unroll
            for (int rr = 0; rr < BM; rr += RPP) {
                float4 v = *(const float4*)(A + (long)(m0 + r + rr) * K + k0 + kc);
                As[r + rr][kc + 0] = to_tf32(v.x);
                As[r + rr][kc + 1] = to_tf32(v.y);
                As[r + rr][kc + 2] = to_tf32(v.z);
                As[r + rr][kc + 3] = to_tf32(v.w);
            }
        }
        // ---- B tile into Bs[k][n] ----
        if constexpr (NT) {
            constexpr int TPR = BK / 4;
            constexpr int RPP = 256 / TPR;
            const int r  = tid / TPR;
            const int kc = (tid % TPR) * 4;
            #pragma unroll
            for (int rr = 0; rr < BN; rr += RPP) {
                float4 v = *(const float4*)(B + (long)(n0 + r + rr) * K + k0 + kc);
                Bs[kc + 0][r + rr] = to_tf32(v.x);
                Bs[kc + 1][r + rr] = to_tf32(v.y);
                Bs[kc + 2][r + rr] = to_tf32(v.z);
                Bs[kc + 3][r + rr] = to_tf32(v.w);
            }
        } else {
            constexpr int TPK = BN / 4;
            constexpr int KPP = 256 / TPK;
            const int kr = tid / TPK;
            const int nc = (tid % TPK) * 4;
            #pragma unroll
            for (int kk = 0; kk < BK; kk += KPP) {
                float4 v = *(const float4*)(B + (long)(k0 + kr + kk) * N + n0 + nc);
                Bs[kr + kk][nc + 0] = to_tf32(v.x);
                Bs[kr + kk][nc + 1] = to_tf32(v.y);
                Bs[kr + kk][nc + 2] = to_tf32(v.z);
                Bs[kr + kk][nc + 3] = to_tf32(v.w);
            }
        }
        __syncthreads();

        #pragma unroll
        for (int kk = 0; kk < BK; kk += 8) {
            uint32_t afr[MT][4];
            #pragma unroll
            for (int mt = 0; mt < MT; mt++) {
                const int row = wm * WTM + mt * 16 + g;
                afr[mt][0] = __float_as_uint(As[row    ][kk + c4    ]);
                afr[mt][1] = __float_as_uint(As[row + 8][kk + c4    ]);
                afr[mt][2] = __float_as_uint(As[row    ][kk + c4 + 4]);
                afr[mt][3] = __float_as_uint(As[row + 8][kk + c4 + 4]);
            }
            uint32_t bfr[NTt][2];
            #pragma unroll
            for (int nt = 0; nt < NTt; nt++) {
                const int n = wn * WTN + nt * 8 + g;
                bfr[nt][0] = __float_as_uint(Bs[kk + c4    ][n]);
                bfr[nt][1] = __float_as_uint(Bs[kk + c4 + 4][n]);
            }
            #pragma unroll
            for (int mt = 0; mt < MT; mt++)
                #pragma unroll
                for (int nt = 0; nt < NTt; nt++)
                    mma_tf32(acc[mt][nt][0], acc[mt][nt][1], acc[mt][nt][2], acc[mt][nt][3],
                             afr[mt][0], afr[mt][1], afr[mt][2], afr[mt][3],
                             bfr[nt][0], bfr[nt][1]);
        }
        __syncthreads();
    }

    // ---- epilogue ----
    #pragma unroll
    for (int mt = 0; mt < MT; mt++) {
        const int row = m0 + wm * WTM + mt * 16 + g;
        #pragma unroll
        for (int nt = 0; nt < NTt; nt++) {
            const int col = n0 + wn * WTN + nt * 8 + c4 * 2;
            float b0 = 0.0f, b1 = 0.0f;
            if (bias) { b0 = bias[col]; b1 = bias[col + 1]; }
            float2 v01 = make_float2(acc[mt][nt][0] + b0, acc[mt][nt][1] + b1);
            float2 v23 = make_float2(acc[mt][nt][2] + b0, acc[mt][nt][3] + b1);
            *(float2*)(C + (long)row * ldc + col)       = v01;
            *(float2*)(C + (long)(row + 8) * ldc + col) = v23;
        }
    }
}

// ---------------- pack qkv [B,N,3,H,D] -> q,k,v [B,H,N,D], scale q ----------------
__global__ void __launch_bounds__(256)
pack_qkv(const float* __restrict__ qkv,
         float* __restrict__ q, float* __restrict__ k,
         float* __restrict__ v)
{
    const long idx = (long)blockIdx.x * blockDim.x + threadIdx.x;     // float4 index
    const long total4 = (long)PB * PN * 3 * PC / 4;
    if (idx >= total4) return;
    const long e = idx * 4;
    const int bn = (int)(e / (3 * PC));
    const int r  = (int)(e % (3 * PC));
    const int s  = r / PC;
    const int r2 = r % PC;
    const int h  = r2 / PD;
    const int d  = r2 % PD;
    const int b  = bn / PN;
    const int n  = bn % PN;

    float4 val = *(const float4*)(qkv + e);
    const long dst = (((long)(b * PH + h) * PN) + n) * PD + d;
    if (s == 0) {
        val.x *= PSCALE; val.y *= PSCALE; val.z *= PSCALE; val.w *= PSCALE;
        *(float4*)(q + dst) = val;
    } else if (s == 1) {
        *(float4*)(k + dst) = val;
    } else {
        *(float4*)(v + dst) = val;
    }
}

// ---------------- fused talking-heads pre-mix + softmax + post-mix + attnscale ----------------
// One block per (b, n) row. In-place on g_s. 384 threads = 12 warps (1 warp/head for softmax).
__global__ void __launch_bounds__(384)
talking_softmax(float* __restrict__ S,
                const float* __restrict__ W_l, const float* __restrict__ b_l,
                const float* __restrict__ W_w, const float* __restrict__ b_w,
                const float* __restrict__ lamb)
{
    extern __shared__ float sraw[];
    float (*sbuf)[PN] = (float(*)[PN])sraw;          // [12][1024] = 48 KB

    __shared__ float wl[PH * PH], ww[PH * PH];
    __shared__ float bl[PH], bw[PH], lam[PH];

    const int tid = threadIdx.x;                      // 0..383
    const int row = blockIdx.x;
    const int b = row >> 10;
    const int n = row & 1023;

    if (tid < PH * PH) { wl[tid] = W_l[tid]; ww[tid] = W_w[tid]; }
    if (tid < PH)      { bl[tid] = b_l[tid]; bw[tid] = b_w[tid]; lam[tid] = lamb[tid]; }

    for (int t = tid; t < PH * (PN / 4); t += 384) {
        const int h  = t >> 8;
        const int m4 = t & 255;
        const long base = (((long)(b * PH + h) * PN) + n) * PN;
        *(float4*)&sbuf[h][m4 * 4] = *(const float4*)(S + base + m4 * 4);
    }
    __syncthreads();

    // pre-softmax talking heads (in-place per column)
    for (int m = tid; m < PN; m += 384) {
        float s[PH], o[PH];
        #pragma unroll
        for (int h = 0; h < PH; h++) s[h] = sbuf[h][m];
        #pragma unroll
        for (int gg = 0; gg < PH; gg++) {
            float t = bl[gg];
            #pragma unroll
            for (int h = 0; h < PH; h++) t += wl[gg * PH + h] * s[h];
            o[gg] = t;
        }
        #pragma unroll
        for (int gg = 0; gg < PH; gg++) sbuf[gg][m] = o[gg];
    }
    __syncthreads();

    // softmax over m: warp w handles head w
    {
        const int w = tid >> 5;
        const int l = tid & 31;
        float mx = -INFINITY;
        for (int m = l; m < PN; m += 32) mx = fmaxf(mx, sbuf[w][m]);
        #pragma unroll
        for (int off = 16; off > 0; off >>= 1)
            mx = fmaxf(mx, __shfl_xor_sync(0xFFFFFFFFu, mx, off));
        float sum = 0.0f;
        for (int m = l; m < PN; m += 32) {
            const float e = __expf(sbuf[w][m] - mx);
            sbuf[w][m] = e;
            sum += e;
        }
        #pragma unroll
        for (int off = 16; off > 0; off >>= 1)
            sum += __shfl_xor_sync(0xFFFFFFFFu, sum, off);
        const float inv = 1.0f / sum;
        for (int m = l; m < PN; m += 32) sbuf[w][m] *= inv;
    }
    __syncthreads();

    // post-softmax talking heads + attnscale (in-place per column)
    const float attn_d = 1.0f / (float)PN;
    for (int m = tid; m < PN; m += 384) {
        float p[PH], o[PH];
        #pragma unroll
        for (int h = 0; h < PH; h++) p[h] = sbuf[h][m];
        #pragma unroll
        for (int gg = 0; gg < PH; gg++) {
            float a = bw[gg];
            #pragma unroll
            for (int h = 0; h < PH; h++) a += ww[gg * PH + h] * p[h];
            o[gg] = a * (1.0f + lam[gg]) - attn_d * lam[gg];
        }
        #pragma unroll
        for (int gg = 0; gg < PH; gg++) sbuf[gg][m] = o[gg];
    }
    __syncthreads();

    for (int t = tid; t < PH * (PN / 4); t += 384) {
        const int h  = t >> 8;
        const int m4 = t & 255;
        const long base = (((long)(b * PH + h) * PN) + n) * PN;
        *(float4*)(S + base + m4 * 4) = *(const float4*)&sbuf[h][m4 * 4];
    }
}

// ---------------- launcher ----------------
extern "C" void kernel_launch(void* const* d_in, const int* in_sizes, int n_in,
                              void* d_out, int out_size)
{
    const float* x      = (const float*)d_in[0];
    const float* W_qkv  = (const float*)d_in[1];
    const float* W_proj = (const float*)d_in[2];
    const float* b_proj = (const float*)d_in[3];
    const float* W_l    = (const float*)d_in[4];
    const float* b_l    = (const float*)d_in[5];
    const float* W_w    = (const float*)d_in[6];
    const float* b_w    = (const float*)d_in[7];
    const float* lamb   = (const float*)d_in[8];
    float* out = (float*)d_out;

    float *qkv, *q, *k, *v, *s, *o;
    cudaGetSymbolAddress((void**)&qkv, g_qkv);
    cudaGetSymbolAddress((void**)&q,   g_q);
    cudaGetSymbolAddress((void**)&k,   g_k);
    cudaGetSymbolAddress((void**)&v,   g_v);
    cudaGetSymbolAddress((void**)&s,   g_s);
    cudaGetSymbolAddress((void**)&o,   g_o);

    const int M  = PB * PN;                   // 4096
    const long qkstride = (long)PN * PD;      // 65536 per (b,h)
    const long sstride  = (long)PN * PN;      // 1048576 per (b,h)

    // 1) QKV projection: [4096,768] x [2304,768]^T -> [4096,2304]
    {
        dim3 grid(3 * PC / 128, M / 128, 1);
        gemm_tf32<128, 128, 32, 4, 2, true><<<grid, 256>>>(
            x, W_qkv, qkv, nullptr, M, 3 * PC, PC,
            0, 0, 0, 0, PH, 3 * PC);
    }

    // 2) pack + scale q
    {
        const long total4 = (long)PB * PN * 3 * PC / 4;
        const int blocks = (int)((total4 + 255) / 256);
        pack_qkv<<<blocks, 256>>>(qkv, q, k, v);
    }

    // 3) scores: per (b,h): S = q k^T, [1024,1024], K=64, batched over 48
    {
        dim3 grid(PN / 128, PN / 128, PB * PH);
        gemm_tf32<128, 128, 32, 4, 2, true><<<grid, 256>>>(
            q, k, s, nullptr, PN, PN, PD,
            qkstride, qkstride, (long)PH * sstride, sstride, PH, PN);
    }

    // 4) fused talking-heads + softmax (in place on s)
    {
        static bool attr_set = false;
        if (!attr_set) {
            cudaFuncSetAttribute(talking_softmax,
                                 cudaFuncAttributeMaxDynamicSharedMemorySize, 49152);
            attr_set = true;
        }
        talking_softmax<<<PB * PN, 384, 49152>>>(s, W_l, b_l, W_w, b_w, lamb);
    }

    // 5) O = A @ V: per (b,h): [1024,1024] x [1024,64], write into [B,N,C] at col h*64
    {
        dim3 grid(PD / 64, PN / 128, PB * PH);
        gemm_tf32<128, 64, 32, 4, 2, false><<<grid, 256>>>(
            s, v, o, nullptr, PN, PD, PN,
            sstride, qkstride, (long)PN * PC, (long)PD, PH, PC);
    }

    // 6) output projection + bias: [4096,768] x [768,768]^T -> d_out
    {
        dim3 grid(PC / 128, M / 128, 1);
        gemm_tf32<128, 128, 32, 4, 2, true><<<grid, 256>>>(
            o, W_proj, out, b_proj, M, PC, PC,
            0, 0, 0, 0, PH, PC);
    }
}

// round 6
// speedup vs baseline: 1.4426x; 1.0702x over previous
#include <cuda_runtime.h>
#include <cuda_fp16.h>
#include <math.h>
#include <stdint.h>

// Problem constants (fixed by reference: B=4, N=1024, C=768, H=12, Dh=64)
#define PB 4
#define PN 1024
#define PC 768
#define PH 12
#define PD 64
#define PSCALE 0.125f   // 64^-0.5

// ---------------- scratch (static device arrays; no allocation) ----------------
__device__ float g_q[(long)PB * PH * PN * PD];           // 12 MB  [B,H,N,D]
__device__ float g_k[(long)PB * PH * PN * PD];
__device__ float g_v[(long)PB * PH * PN * PD];
__device__ float g_s[(long)PB * PH * PN * PN];           // 192 MB [B,H,N,N]
__device__ float g_o[(long)PB * PN * PC];                // 12 MB  [B,N,C]

__device__ __forceinline__ uint32_t smem_u32(const void* p) {
    return (uint32_t)__cvta_generic_to_shared(p);
}

__device__ __forceinline__ void ldmatrix_x4(uint32_t& r0, uint32_t& r1, uint32_t& r2, uint32_t& r3,
                                            uint32_t addr) {
    asm volatile("ldmatrix.sync.aligned.m8n8.x4.shared.b16 {%0,%1,%2,%3}, [%4];"
                 : "=r"(r0), "=r"(r1), "=r"(r2), "=r"(r3) : "r"(addr));
}
__device__ __forceinline__ void ldmatrix_x2(uint32_t& r0, uint32_t& r1, uint32_t addr) {
    asm volatile("ldmatrix.sync.aligned.m8n8.x2.shared.b16 {%0,%1}, [%2];"
                 : "=r"(r0), "=r"(r1) : "r"(addr));
}
__device__ __forceinline__ void mma_f16(float& c0, float& c1, float& c2, float& c3,
                                        uint32_t a0, uint32_t a1, uint32_t a2, uint32_t a3,
                                        uint32_t b0, uint32_t b1) {
    asm volatile(
        "mma.sync.aligned.m16n8k16.row.col.f32.f16.f16.f32 "
        "{%0,%1,%2,%3}, {%4,%5,%6,%7}, {%8,%9}, {%0,%1,%2,%3};"
        : "+f"(c0), "+f"(c1), "+f"(c2), "+f"(c3)
        : "r"(a0), "r"(a1), "r"(a2), "r"(a3), "r"(b0), "r"(b1));
}

__device__ __forceinline__ void f4_to_h4(__half* dst, float4 v) {
    dst[0] = __float2half_rn(v.x);
    dst[1] = __float2half_rn(v.y);
    dst[2] = __float2half_rn(v.z);
    dst[3] = __float2half_rn(v.w);
}

// ---------------- fp16 tensor-core GEMM (fp32 gmem in/out) ----------------
// C[M,N] = A[M,K] * op(B), A row-major. NT=true: B is [N,K] (C=A B^T); else B is [K,N].
// Batched over blockIdx.z. wmode: 0 = plain write (+bias), 1 = qkv-pack write to qp/kp/vp.
template<int BM, int BN, int BK, bool NT>
__global__ void __launch_bounds__(256)
gemm_f16(const float* __restrict__ Ab, const float* __restrict__ Bb,
         float* __restrict__ Cb, const float* __restrict__ bias,
         int M, int N, int K,
         long sA, long sB, long sCb, long sCh, int CB, int ldc,
         int wmode, float* __restrict__ qp, float* __restrict__ kp, float* __restrict__ vp)
{
    constexpr int BKH = BK + 8;            // fp16 elems per row (80B stride: LDSM conflict-free)
    constexpr int WM = 4, WN = 2;
    constexpr int WTM = BM / WM;           // 32
    constexpr int WTN = BN / WN;           // 64 or 32
    constexpr int MT  = WTM / 16;          // 2
    constexpr int NTt = WTN / 8;           // 8 or 4
    // A tile load geometry
    constexpr int ATPR = BK / 4;           // threads per A row
    constexpr int ARPP = 256 / ATPR;       // A rows per pass
    constexpr int APASS = BM / ARPP;
    // B tile load geometry
    constexpr int BTPR = BK / 4;
    constexpr int BRPP = 256 / BTPR;
    constexpr int BPASS_NT = BN / BRPP;
    constexpr int BTPK = BN / 4;
    constexpr int BKPP = 256 / BTPK;
    constexpr int BPASS_NN = BK / BKPP;
    constexpr int BPASS = NT ? BPASS_NT : BPASS_NN;

    __shared__ __half As[2][BM][BKH];
    __shared__ __half Bs[2][BN][BKH];      // stored n-major (k contiguous) for both layouts

    const int z = blockIdx.z;
    const float* A = Ab + (long)z * sA;
    const float* B = Bb + (long)z * sB;
    float* C = Cb + (long)(z / CB) * sCb + (long)(z % CB) * sCh;

    const int tid  = threadIdx.x;
    const int warp = tid >> 5;
    const int lane = tid & 31;
    const int g    = lane >> 2;
    const int c4   = lane & 3;
    const int wm   = warp % WM;
    const int wn   = warp / WM;

    const int m0 = blockIdx.y * BM;
    const int n0 = blockIdx.x * BN;

    float acc[MT][NTt][4];
    #pragma unroll
    for (int i = 0; i < MT; i++)
        #pragma unroll
        for (int j = 0; j < NTt; j++)
            #pragma unroll
            for (int r = 0; r < 4; r++) acc[i][j][r] = 0.0f;

    const int nk = K / BK;

    float4 areg[APASS];
    float4 breg[BPASS];

    // ---- LDG helpers (into registers) ----
    auto ldg_tiles = [&](int k0) {
        {
            const int r  = tid / ATPR;
            const int kc = (tid % ATPR) * 4;
            #pragma unroll
            for (int p = 0; p < APASS; p++)
                areg[p] = *(const float4*)(A + (long)(m0 + r + p * ARPP) * K + k0 + kc);
        }
        if constexpr (NT) {
            const int r  = tid / BTPR;
            const int kc = (tid % BTPR) * 4;
            #pragma unroll
            for (int p = 0; p < BPASS; p++)
                breg[p] = *(const float4*)(B + (long)(n0 + r + p * BRPP) * K + k0 + kc);
        } else {
            const int kr = tid / BTPK;
            const int nc = (tid % BTPK) * 4;
            #pragma unroll
            for (int p = 0; p < BPASS; p++)
                breg[p] = *(const float4*)(B + (long)(k0 + kr + p * BKPP) * N + n0 + nc);
        }
    };
    auto sts_tiles = [&](int buf) {
        {
            const int r  = tid / ATPR;
            const int kc = (tid % ATPR) * 4;
            #pragma unroll
            for (int p = 0; p < APASS; p++)
                f4_to_h4(&As[buf][r + p * ARPP][kc], areg[p]);
        }
        if constexpr (NT) {
            const int r  = tid / BTPR;
            const int kc = (tid % BTPR) * 4;
            #pragma unroll
            for (int p = 0; p < BPASS; p++)
                f4_to_h4(&Bs[buf][r + p * BRPP][kc], breg[p]);
        } else {
            const int kr = tid / BTPK;
            const int nc = (tid % BTPK) * 4;
            #pragma unroll
            for (int p = 0; p < BPASS; p++) {
                const int k = kr + p * BKPP;
                Bs[buf][nc + 0][k] = __float2half_rn(breg[p].x);
                Bs[buf][nc + 1][k] = __float2half_rn(breg[p].y);
                Bs[buf][nc + 2][k] = __float2half_rn(breg[p].z);
                Bs[buf][nc + 3][k] = __float2half_rn(breg[p].w);
            }
        }
    };

    // prologue
    ldg_tiles(0);
    sts_tiles(0);
    __syncthreads();

    for (int i = 0; i < nk; i++) {
        const int buf = i & 1;
        const bool has_next = (i + 1 < nk);
        if (has_next) ldg_tiles((i + 1) * BK);

        // ---- compute from smem[buf] ----
        #pragma unroll
        for (int kk = 0; kk < BK; kk += 16) {
            uint32_t afr[MT][4];
            #pragma unroll
            for (int mt = 0; mt < MT; mt++) {
                const int rbase = wm * WTM + mt * 16;
                uint32_t addr = smem_u32(&As[buf][rbase + (lane & 15)][kk + ((lane >> 4) << 3)]);
                ldmatrix_x4(afr[mt][0], afr[mt][1], afr[mt][2], afr[mt][3], addr);
            }
            uint32_t bfr[NTt][2];
            #pragma unroll
            for (int nt = 0; nt < NTt; nt++) {
                const int nb = wn * WTN + nt * 8;
                uint32_t addr = smem_u32(&Bs[buf][nb + (lane & 7)][kk + (((lane >> 3) & 1) << 3)]);
                ldmatrix_x2(bfr[nt][0], bfr[nt][1], addr);
            }
            #pragma unroll
            for (int mt = 0; mt < MT; mt++)
                #pragma unroll
                for (int nt = 0; nt < NTt; nt++)
                    mma_f16(acc[mt][nt][0], acc[mt][nt][1], acc[mt][nt][2], acc[mt][nt][3],
                            afr[mt][0], afr[mt][1], afr[mt][2], afr[mt][3],
                            bfr[nt][0], bfr[nt][1]);
        }

        if (has_next) sts_tiles(buf ^ 1);
        __syncthreads();
    }

    // ---- epilogue ----
    if (wmode == 0) {
        #pragma unroll
        for (int mt = 0; mt < MT; mt++) {
            const int row = m0 + wm * WTM + mt * 16 + g;
            #pragma unroll
            for (int nt = 0; nt < NTt; nt++) {
                const int col = n0 + wn * WTN + nt * 8 + c4 * 2;
                float b0 = 0.0f, b1 = 0.0f;
                if (bias) { b0 = bias[col]; b1 = bias[col + 1]; }
                *(float2*)(C + (long)row * ldc + col) =
                    make_float2(acc[mt][nt][0] + b0, acc[mt][nt][1] + b1);
                *(float2*)(C + (long)(row + 8) * ldc + col) =
                    make_float2(acc[mt][nt][2] + b0, acc[mt][nt][3] + b1);
            }
        }
    } else {
        // qkv pack: row = b*1024+n, col in [0,2304) -> s,h,d; scale q by PSCALE
        #pragma unroll
        for (int mt = 0; mt < MT; mt++) {
            const int row = m0 + wm * WTM + mt * 16 + g;
            const int b = row >> 10;
            const int n = row & 1023;
            #pragma unroll
            for (int nt = 0; nt < NTt; nt++) {
                const int col = n0 + wn * WTN + nt * 8 + c4 * 2;
                const int s  = col / PC;
                const int r2 = col % PC;
                const int h  = r2 >> 6;
                const int d  = r2 & 63;
                float* dstb = (s == 0) ? qp : (s == 1) ? kp : vp;
                const float sc = (s == 0) ? PSCALE : 1.0f;
                const long base = (((long)(b * PH + h) * PN) + n) * PD + d;
                *(float2*)(dstb + base) =
                    make_float2(acc[mt][nt][0] * sc, acc[mt][nt][1] * sc);
                *(float2*)(dstb + base + 8L * PD) =
                    make_float2(acc[mt][nt][2] * sc, acc[mt][nt][3] * sc);
            }
        }
    }
}

// ---------------- fused talking-heads pre-mix + softmax + post-mix + attnscale ----------------
__global__ void __launch_bounds__(384)
talking_softmax(float* __restrict__ S,
                const float* __restrict__ W_l, const float* __restrict__ b_l,
                const float* __restrict__ W_w, const float* __restrict__ b_w,
                const float* __restrict__ lamb)
{
    extern __shared__ float sraw[];
    float (*sbuf)[PN] = (float(*)[PN])sraw;          // [12][1024] = 48 KB

    __shared__ float wl[PH * PH], ww[PH * PH];
    __shared__ float bl[PH], bw[PH], lam[PH];

    const int tid = threadIdx.x;
    const int row = blockIdx.x;
    const int b = row >> 10;
    const int n = row & 1023;

    if (tid < PH * PH) { wl[tid] = W_l[tid]; ww[tid] = W_w[tid]; }
    if (tid < PH)      { bl[tid] = b_l[tid]; bw[tid] = b_w[tid]; lam[tid] = lamb[tid]; }

    for (int t = tid; t < PH * (PN / 4); t += 384) {
        const int h  = t >> 8;
        const int m4 = t & 255;
        const long base = (((long)(b * PH + h) * PN) + n) * PN;
        *(float4*)&sbuf[h][m4 * 4] = *(const float4*)(S + base + m4 * 4);
    }
    __syncthreads();

    for (int m = tid; m < PN; m += 384) {
        float s[PH], o[PH];
        #pragma unroll
        for (int h = 0; h < PH; h++) s[h] = sbuf[h][m];
        #pragma unroll
        for (int gg = 0; gg < PH; gg++) {
            float t = bl[gg];
            #pragma unroll
            for (int h = 0; h < PH; h++) t += wl[gg * PH + h] * s[h];
            o[gg] = t;
        }
        #pragma unroll
        for (int gg = 0; gg < PH; gg++) sbuf[gg][m] = o[gg];
    }
    __syncthreads();

    {
        const int w = tid >> 5;
        const int l = tid & 31;
        float mx = -INFINITY;
        for (int m = l; m < PN; m += 32) mx = fmaxf(mx, sbuf[w][m]);
        #pragma unroll
        for (int off = 16; off > 0; off >>= 1)
            mx = fmaxf(mx, __shfl_xor_sync(0xFFFFFFFFu, mx, off));
        float sum = 0.0f;
        for (int m = l; m < PN; m += 32) {
            const float e = __expf(sbuf[w][m] - mx);
            sbuf[w][m] = e;
            sum += e;
        }
        #pragma unroll
        for (int off = 16; off > 0; off >>= 1)
            sum += __shfl_xor_sync(0xFFFFFFFFu, sum, off);
        const float inv = 1.0f / sum;
        for (int m = l; m < PN; m += 32) sbuf[w][m] *= inv;
    }
    __syncthreads();

    const float attn_d = 1.0f / (float)PN;
    for (int m = tid; m < PN; m += 384) {
        float p[PH], o[PH];
        #pragma unroll
        for (int h = 0; h < PH; h++) p[h] = sbuf[h][m];
        #pragma unroll
        for (int gg = 0; gg < PH; gg++) {
            float a = bw[gg];
            #pragma unroll
            for (int h = 0; h < PH; h++) a += ww[gg * PH + h] * p[h];
            o[gg] = a * (1.0f + lam[gg]) - attn_d * lam[gg];
        }
        #pragma unroll
        for (int gg = 0; gg < PH; gg++) sbuf[gg][m] = o[gg];
    }
    __syncthreads();

    for (int t = tid; t < PH * (PN / 4); t += 384) {
        const int h  = t >> 8;
        const int m4 = t & 255;
        const long base = (((long)(b * PH + h) * PN) + n) * PN;
        *(float4*)(S + base + m4 * 4) = *(const float4*)&sbuf[h][m4 * 4];
    }
}

// ---------------- launcher ----------------
extern "C" void kernel_launch(void* const* d_in, const int* in_sizes, int n_in,
                              void* d_out, int out_size)
{
    const float* x      = (const float*)d_in[0];
    const float* W_qkv  = (const float*)d_in[1];
    const float* W_proj = (const float*)d_in[2];
    const float* b_proj = (const float*)d_in[3];
    const float* W_l    = (const float*)d_in[4];
    const float* b_l    = (const float*)d_in[5];
    const float* W_w    = (const float*)d_in[6];
    const float* b_w    = (const float*)d_in[7];
    const float* lamb   = (const float*)d_in[8];
    float* out = (float*)d_out;

    float *q, *k, *v, *s, *o;
    cudaGetSymbolAddress((void**)&q, g_q);
    cudaGetSymbolAddress((void**)&k, g_k);
    cudaGetSymbolAddress((void**)&v, g_v);
    cudaGetSymbolAddress((void**)&s, g_s);
    cudaGetSymbolAddress((void**)&o, g_o);

    const int M  = PB * PN;                   // 4096
    const long qkstride = (long)PN * PD;      // per (b,h)
    const long sstride  = (long)PN * PN;      // per (b,h)

    // 1) QKV projection + pack + q-scale: [4096,768] x [2304,768]^T
    {
        dim3 grid(3 * PC / 128, M / 128, 1);
        gemm_f16<128, 128, 32, true><<<grid, 256>>>(
            x, W_qkv, nullptr, nullptr, M, 3 * PC, PC,
            0, 0, 0, 0, PH, 0, 1, q, k, v);
    }

    // 2) scores: per (b,h): S = q k^T, [1024,1024], K=64
    {
        dim3 grid(PN / 128, PN / 128, PB * PH);
        gemm_f16<128, 128, 32, true><<<grid, 256>>>(
            q, k, s, nullptr, PN, PN, PD,
            qkstride, qkstride, (long)PH * sstride, sstride, PH, PN,
            0, nullptr, nullptr, nullptr);
    }

    // 3) fused talking-heads + softmax (in place on s)
    {
        static bool attr_set = false;
        if (!attr_set) {
            cudaFuncSetAttribute(talking_softmax,
                                 cudaFuncAttributeMaxDynamicSharedMemorySize, 49152);
            attr_set = true;
        }
        talking_softmax<<<PB * PN, 384, 49152>>>(s, W_l, b_l, W_w, b_w, lamb);
    }

    // 4) O = A @ V: per (b,h): [1024,1024] x [1024,64] -> o[B,N,C] col block h
    {
        dim3 grid(PD / 64, PN / 128, PB * PH);
        gemm_f16<128, 64, 32, false><<<grid, 256>>>(
            s, v, o, nullptr, PN, PD, PN,
            sstride, qkstride, (long)PN * PC, (long)PD, PH, PC,
            0, nullptr, nullptr, nullptr);
    }

    // 5) output projection + bias: [4096,768] x [768,768]^T -> d_out
    {
        dim3 grid(PC / 128, M / 128, 1);
        gemm_f16<128, 128, 32, true><<<grid, 256>>>(
            o, W_proj, out, b_proj, M, PC, PC,
            0, 0, 0, 0, PH, PC, 0, nullptr, nullptr, nullptr);
    }
}

// round 7
// speedup vs baseline: 1.5183x; 1.0525x over previous
#include <cuda_runtime.h>
#include <cuda_fp16.h>
#include <math.h>
#include <stdint.h>

// Problem constants (fixed: B=4, N=1024, C=768, H=12, Dh=64)
#define PB 4
#define PN 1024
#define PC 768
#define PH 12
#define PD 64
#define PSCALE 0.125f

// ---------------- scratch (static device arrays; no allocation) ----------------
__device__ __half g_xh[(long)PB * PN * PC];            // 6 MB
__device__ __half g_wqh[(long)3 * PC * PC];            // 3.4 MB
__device__ __half g_wph[(long)PC * PC];                // 1.1 MB
__device__ __half g_qh[(long)PB * PH * PN * PD];       // 6 MB [B,H,N,D]
__device__ __half g_kh[(long)PB * PH * PN * PD];
__device__ __half g_vh[(long)PB * PH * PN * PD];
__device__ float  g_s [(long)PB * PH * PN * PN];       // 192 MB [B,H,N,N] pre-softmax
__device__ __half g_s2[(long)PB * PH * PN * PN];       // 96 MB  post-softmax probs
__device__ __half g_oh[(long)PB * PN * PC];            // 6 MB [B,N,C]

__device__ __forceinline__ uint32_t smem_u32(const void* p) {
    return (uint32_t)__cvta_generic_to_shared(p);
}
__device__ __forceinline__ void cp_async16(uint32_t dst, const void* src) {
    asm volatile("cp.async.cg.shared.global [%0], [%1], 16;" :: "r"(dst), "l"(src));
}
__device__ __forceinline__ void cp_commit() {
    asm volatile("cp.async.commit_group;");
}
template<int N_>
__device__ __forceinline__ void cp_wait() {
    asm volatile("cp.async.wait_group %0;" :: "n"(N_));
}
__device__ __forceinline__ void ldmatrix_x4(uint32_t& r0, uint32_t& r1, uint32_t& r2, uint32_t& r3,
                                            uint32_t addr) {
    asm volatile("ldmatrix.sync.aligned.m8n8.x4.shared.b16 {%0,%1,%2,%3}, [%4];"
                 : "=r"(r0), "=r"(r1), "=r"(r2), "=r"(r3) : "r"(addr));
}
__device__ __forceinline__ void ldmatrix_x2(uint32_t& r0, uint32_t& r1, uint32_t addr) {
    asm volatile("ldmatrix.sync.aligned.m8n8.x2.shared.b16 {%0,%1}, [%2];"
                 : "=r"(r0), "=r"(r1) : "r"(addr));
}
__device__ __forceinline__ void ldmatrix_x2_trans(uint32_t& r0, uint32_t& r1, uint32_t addr) {
    asm volatile("ldmatrix.sync.aligned.m8n8.x2.trans.shared.b16 {%0,%1}, [%2];"
                 : "=r"(r0), "=r"(r1) : "r"(addr));
}
__device__ __forceinline__ void mma_f16(float& c0, float& c1, float& c2, float& c3,
                                        uint32_t a0, uint32_t a1, uint32_t a2, uint32_t a3,
                                        uint32_t b0, uint32_t b1) {
    asm volatile(
        "mma.sync.aligned.m16n8k16.row.col.f32.f16.f16.f32 "
        "{%0,%1,%2,%3}, {%4,%5,%6,%7}, {%8,%9}, {%0,%1,%2,%3};"
        : "+f"(c0), "+f"(c1), "+f"(c2), "+f"(c3)
        : "r"(a0), "r"(a1), "r"(a2), "r"(a3), "r"(b0), "r"(b1));
}

// fast exp for x<=0 (FMA pipe, no MUFU): exp(x) = 2^(x*log2e)
__device__ __forceinline__ float fexp(float x) {
    float y = fmaxf(x * 1.4426950408889634f, -80.0f);
    float t = y + 12582912.0f;               // round-to-nearest-int magic (1.5*2^23)
    int   n = __float_as_int(t) - 0x4B400000;
    float r = y - (t - 12582912.0f);         // r in [-0.5, 0.5]
    float p = 1.3333558e-3f;
    p = fmaf(p, r, 9.6181291e-3f);
    p = fmaf(p, r, 5.5504109e-2f);
    p = fmaf(p, r, 2.4022651e-1f);
    p = fmaf(p, r, 6.9314718e-1f);
    p = fmaf(p, r, 1.0f);
    return __int_as_float(__float_as_int(p) + (n << 23));
}

// ---------------- fp32 -> fp16 convert (elementwise, float4-vectorized) ----------------
__global__ void __launch_bounds__(256)
f2h(const float* __restrict__ s, __half* __restrict__ d, int n4)
{
    int i = blockIdx.x * blockDim.x + threadIdx.x;
    if (i < n4) {
        float4 v = ((const float4*)s)[i];
        ((__half2*)d)[i * 2]     = __floats2half2_rn(v.x, v.y);
        ((__half2*)d)[i * 2 + 1] = __floats2half2_rn(v.z, v.w);
    }
}

// ---------------- fp16 cp.async pipelined tensor-core GEMM ----------------
// A: __half [M,K] row-major (k-contig). B: BNT ? [N,K] : [K,N] __half.
// Batched over blockIdx.z: A += z*sA, B += z*sB, C += (z/CB)*sCb + (z%CB)*sCh (elements).
// OUTM: 0 = fp32 out (+bias), 1 = fp16 out, 2 = qkv-pack fp16 (q scaled).
template<int BM, int BN, int BK, int STAGES, bool BNT, int OUTM>
__global__ void __launch_bounds__(256)
gemm_h(const __half* __restrict__ Ab, const __half* __restrict__ Bb,
       void* __restrict__ Cb, const float* __restrict__ bias,
       int M, int N, int K,
       long sA, long sB, long sCb, long sCh, int CB, int ldc,
       __half* __restrict__ qp, __half* __restrict__ kp, __half* __restrict__ vp)
{
    constexpr int BKP = BK + 8;            // A row stride (halves), 16B-aligned
    constexpr int BNP = BN + 8;            // NN-B row stride (halves), 16B-aligned
    constexpr int WM = 4, WN = 2;
    constexpr int WTM = BM / WM;           // 32
    constexpr int WTN = BN / WN;
    constexpr int MT  = WTM / 16;          // 2
    constexpr int NTt = WTN / 8;
    constexpr int ASTG = BM * BKP;         // halves per A stage
    constexpr int BSTG = BNT ? (BN * BKP) : (BK * BNP);
    // A load geometry: 16B = 8 halves
    constexpr int ATPR  = BK / 8;
    constexpr int ARPP  = 256 / ATPR;
    constexpr int APASS = BM / ARPP;
    // B load geometry
    constexpr int BTPR_NT  = BK / 8;
    constexpr int BRPP_NT  = 256 / BTPR_NT;
    constexpr int BPASS_NT = BN / BRPP_NT;
    constexpr int BTPR_NN  = BN / 8;
    constexpr int BRPP_NN  = 256 / BTPR_NN;
    constexpr int BPASS_NN = (BK + BRPP_NN - 1) / BRPP_NN;

    extern __shared__ __half sm[];
    __half* Asm = sm;
    __half* Bsm = sm + (long)STAGES * ASTG;

    const int z = blockIdx.z;
    const __half* A = Ab + (long)z * sA;
    const __half* B = Bb + (long)z * sB;

    const int tid  = threadIdx.x;
    const int warp = tid >> 5;
    const int lane = tid & 31;
    const int g    = lane >> 2;
    const int c4   = lane & 3;
    const int wm   = warp % WM;
    const int wn   = warp / WM;

    const int m0 = blockIdx.y * BM;
    const int n0 = blockIdx.x * BN;

    float acc[MT][NTt][4];
    #pragma unroll
    for (int i = 0; i < MT; i++)
        #pragma unroll
        for (int j = 0; j < NTt; j++)
            #pragma unroll
            for (int r = 0; r < 4; r++) acc[i][j][r] = 0.0f;

    const int nk = K / BK;

    auto load_stage = [&](int st, int k0) {
        {
            const int r  = tid / ATPR;
            const int kc = (tid % ATPR) * 8;
            #pragma unroll
            for (int p = 0; p < APASS; p++)
                cp_async16(smem_u32(Asm + (long)st * ASTG + (r + p * ARPP) * BKP + kc),
                           A + (long)(m0 + r + p * ARPP) * K + k0 + kc);
        }
        if constexpr (BNT) {
            const int r  = tid / BTPR_NT;
            const int kc = (tid % BTPR_NT) * 8;
            #pragma unroll
            for (int p = 0; p < BPASS_NT; p++)
                cp_async16(smem_u32(Bsm + (long)st * BSTG + (r + p * BRPP_NT) * BKP + kc),
                           B + (long)(n0 + r + p * BRPP_NT) * K + k0 + kc);
        } else {
            const int kr = tid / BTPR_NN;
            const int nc = (tid % BTPR_NN) * 8;
            #pragma unroll
            for (int p = 0; p < BPASS_NN; p++) {
                const int k = kr + p * BRPP_NN;
                if (k < BK)
                    cp_async16(smem_u32(Bsm + (long)st * BSTG + k * BNP + nc),
                               B + (long)(k0 + k) * N + n0 + nc);
            }
        }
    };

    auto compute_stage = [&](int st) {
        const __half* As = Asm + (long)st * ASTG;
        const __half* Bs = Bsm + (long)st * BSTG;
        #pragma unroll
        for (int kk = 0; kk < BK; kk += 16) {
            uint32_t afr[MT][4];
            #pragma unroll
            for (int mt = 0; mt < MT; mt++) {
                const int rbase = wm * WTM + mt * 16;
                uint32_t addr = smem_u32(As + (rbase + (lane & 15)) * BKP + kk + ((lane >> 4) << 3));
                ldmatrix_x4(afr[mt][0], afr[mt][1], afr[mt][2], afr[mt][3], addr);
            }
            uint32_t bfr[NTt][2];
            #pragma unroll
            for (int nt = 0; nt < NTt; nt++) {
                const int nb = wn * WTN + nt * 8;
                if constexpr (BNT) {
                    uint32_t addr = smem_u32(Bs + (nb + (lane & 7)) * BKP + kk + (((lane >> 3) & 1) << 3));
                    ldmatrix_x2(bfr[nt][0], bfr[nt][1], addr);
                } else {
                    uint32_t addr = smem_u32(Bs + (kk + (lane & 15)) * BNP + nb);
                    ldmatrix_x2_trans(bfr[nt][0], bfr[nt][1], addr);
                }
            }
            #pragma unroll
            for (int mt = 0; mt < MT; mt++)
                #pragma unroll
                for (int nt = 0; nt < NTt; nt++)
                    mma_f16(acc[mt][nt][0], acc[mt][nt][1], acc[mt][nt][2], acc[mt][nt][3],
                            afr[mt][0], afr[mt][1], afr[mt][2], afr[mt][3],
                            bfr[nt][0], bfr[nt][1]);
        }
    };

    // ---- pipelined mainloop ----
    #pragma unroll
    for (int s = 0; s < STAGES - 1; s++) {
        if (s < nk) load_stage(s, s * BK);
        cp_commit();
    }
    for (int i = 0; i < nk; i++) {
        cp_wait<STAGES - 2>();
        __syncthreads();
        compute_stage(i % STAGES);
        const int nx = i + STAGES - 1;
        if (nx < nk) load_stage(nx % STAGES, nx * BK);
        cp_commit();
        __syncthreads();
    }

    // ---- epilogue ----
    if constexpr (OUTM == 0) {
        float* C = (float*)Cb + (long)(z / CB) * sCb + (long)(z % CB) * sCh;
        #pragma unroll
        for (int mt = 0; mt < MT; mt++) {
            const int row = m0 + wm * WTM + mt * 16 + g;
            #pragma unroll
            for (int nt = 0; nt < NTt; nt++) {
                const int col = n0 + wn * WTN + nt * 8 + c4 * 2;
                float b0 = 0.0f, b1 = 0.0f;
                if (bias) { b0 = bias[col]; b1 = bias[col + 1]; }
                *(float2*)(C + (long)row * ldc + col) =
                    make_float2(acc[mt][nt][0] + b0, acc[mt][nt][1] + b1);
                *(float2*)(C + (long)(row + 8) * ldc + col) =
                    make_float2(acc[mt][nt][2] + b0, acc[mt][nt][3] + b1);
            }
        }
    } else if constexpr (OUTM == 1) {
        __half* C = (__half*)Cb + (long)(z / CB) * sCb + (long)(z % CB) * sCh;
        #pragma unroll
        for (int mt = 0; mt < MT; mt++) {
            const int row = m0 + wm * WTM + mt * 16 + g;
            #pragma unroll
            for (int nt = 0; nt < NTt; nt++) {
                const int col = n0 + wn * WTN + nt * 8 + c4 * 2;
                *(__half2*)(C + (long)row * ldc + col) =
                    __floats2half2_rn(acc[mt][nt][0], acc[mt][nt][1]);
                *(__half2*)(C + (long)(row + 8) * ldc + col) =
                    __floats2half2_rn(acc[mt][nt][2], acc[mt][nt][3]);
            }
        }
    } else {
        // qkv pack: row in [0,4096) -> (b,n); col in [0,2304) -> (s,h,d)
        #pragma unroll
        for (int mt = 0; mt < MT; mt++) {
            const int row = m0 + wm * WTM + mt * 16 + g;
            const int b = row >> 10;
            const int n = row & 1023;
            #pragma unroll
            for (int nt = 0; nt < NTt; nt++) {
                const int col = n0 + wn * WTN + nt * 8 + c4 * 2;
                const int s  = col / PC;
                const int r2 = col % PC;
                const int h  = r2 >> 6;
                const int d  = r2 & 63;
                __half* dstb = (s == 0) ? qp : (s == 1) ? kp : vp;
                const float sc = (s == 0) ? PSCALE : 1.0f;
                const long base = (((long)(b * PH + h) * PN) + n) * PD + d;
                *(__half2*)(dstb + base) =
                    __floats2half2_rn(acc[mt][nt][0] * sc, acc[mt][nt][1] * sc);
                *(__half2*)(dstb + base + 8L * PD) =
                    __floats2half2_rn(acc[mt][nt][2] * sc, acc[mt][nt][3] * sc);
            }
        }
    }
}

// ---------------- fused talking-heads + softmax (fp32 in, fp16 out) ----------------
__global__ void __launch_bounds__(384)
talking_softmax(const float* __restrict__ S, __half* __restrict__ S2,
                const float* __restrict__ W_l, const float* __restrict__ b_l,
                const float* __restrict__ W_w, const float* __restrict__ b_w,
                const float* __restrict__ lamb)
{
    extern __shared__ float sraw[];
    float (*sbuf)[PN] = (float(*)[PN])sraw;          // [12][1024] = 48 KB

    __shared__ float wl[PH * PH], ww[PH * PH];
    __shared__ float bl[PH], bw[PH], lam[PH];

    const int tid = threadIdx.x;
    const int row = blockIdx.x;
    const int b = row >> 10;
    const int n = row & 1023;

    if (tid < PH * PH) { wl[tid] = W_l[tid]; ww[tid] = W_w[tid]; }
    if (tid < PH)      { bl[tid] = b_l[tid]; bw[tid] = b_w[tid]; lam[tid] = lamb[tid]; }

    for (int t = tid; t < PH * (PN / 4); t += 384) {
        const int h  = t >> 8;
        const int m4 = t & 255;
        const long base = (((long)(b * PH + h) * PN) + n) * PN;
        *(float4*)&sbuf[h][m4 * 4] = *(const float4*)(S + base + m4 * 4);
    }
    __syncthreads();

    // pre-softmax head mix
    for (int m = tid; m < PN; m += 384) {
        float s[PH], o[PH];
        #pragma unroll
        for (int h = 0; h < PH; h++) s[h] = sbuf[h][m];
        #pragma unroll
        for (int gg = 0; gg < PH; gg++) {
            float t = bl[gg];
            #pragma unroll
            for (int h = 0; h < PH; h++) t += wl[gg * PH + h] * s[h];
            o[gg] = t;
        }
        #pragma unroll
        for (int gg = 0; gg < PH; gg++) sbuf[gg][m] = o[gg];
    }
    __syncthreads();

    // softmax per head (warp w -> head w), FMA-pipe exp
    {
        const int w = tid >> 5;
        const int l = tid & 31;
        float mx = -INFINITY;
        for (int m = l; m < PN; m += 32) mx = fmaxf(mx, sbuf[w][m]);
        #pragma unroll
        for (int off = 16; off > 0; off >>= 1)
            mx = fmaxf(mx, __shfl_xor_sync(0xFFFFFFFFu, mx, off));
        float sum = 0.0f;
        for (int m = l; m < PN; m += 32) {
            const float e = fexp(sbuf[w][m] - mx);
            sbuf[w][m] = e;
            sum += e;
        }
        #pragma unroll
        for (int off = 16; off > 0; off >>= 1)
            sum += __shfl_xor_sync(0xFFFFFFFFu, sum, off);
        const float inv = 1.0f / sum;
        for (int m = l; m < PN; m += 32) sbuf[w][m] *= inv;
    }
    __syncthreads();

    // post-softmax head mix + attnscale
    const float attn_d = 1.0f / (float)PN;
    for (int m = tid; m < PN; m += 384) {
        float p[PH], o[PH];
        #pragma unroll
        for (int h = 0; h < PH; h++) p[h] = sbuf[h][m];
        #pragma unroll
        for (int gg = 0; gg < PH; gg++) {
            float a = bw[gg];
            #pragma unroll
            for (int h = 0; h < PH; h++) a += ww[gg * PH + h] * p[h];
            o[gg] = a * (1.0f + lam[gg]) - attn_d * lam[gg];
        }
        #pragma unroll
        for (int gg = 0; gg < PH; gg++) sbuf[gg][m] = o[gg];
    }
    __syncthreads();

    // store post-softmax probs as fp16
    for (int t = tid; t < PH * (PN / 4); t += 384) {
        const int h  = t >> 8;
        const int m4 = t & 255;
        const long base = (((long)(b * PH + h) * PN) + n) * PN;
        float4 v = *(const float4*)&sbuf[h][m4 * 4];
        __half2* dst = (__half2*)(S2 + base + m4 * 4);
        dst[0] = __floats2half2_rn(v.x, v.y);
        dst[1] = __floats2half2_rn(v.z, v.w);
    }
}

// ---------------- launcher ----------------
extern "C" void kernel_launch(void* const* d_in, const int* in_sizes, int n_in,
                              void* d_out, int out_size)
{
    const float* x      = (const float*)d_in[0];
    const float* W_qkv  = (const float*)d_in[1];
    const float* W_proj = (const float*)d_in[2];
    const float* b_proj = (const float*)d_in[3];
    const float* W_l    = (const float*)d_in[4];
    const float* b_l    = (const float*)d_in[5];
    const float* W_w    = (const float*)d_in[6];
    const float* b_w    = (const float*)d_in[7];
    const float* lamb   = (const float*)d_in[8];
    float* out = (float*)d_out;

    __half *xh, *wqh, *wph, *qh, *kh, *vh, *s2, *oh;
    float *s;
    cudaGetSymbolAddress((void**)&xh,  g_xh);
    cudaGetSymbolAddress((void**)&wqh, g_wqh);
    cudaGetSymbolAddress((void**)&wph, g_wph);
    cudaGetSymbolAddress((void**)&qh,  g_qh);
    cudaGetSymbolAddress((void**)&kh,  g_kh);
    cudaGetSymbolAddress((void**)&vh,  g_vh);
    cudaGetSymbolAddress((void**)&s,   g_s);
    cudaGetSymbolAddress((void**)&s2,  g_s2);
    cudaGetSymbolAddress((void**)&oh,  g_oh);

    const int M = PB * PN;                     // 4096
    const long qkstride = (long)PN * PD;       // per (b,h)
    const long sstride  = (long)PN * PN;       // per (b,h)

    // smem sizes per instantiation
    constexpr int SM_A  = (3 * 128 * 40 + 3 * 128 * 40) * 2;   // 61440 (BNT 128x128x32, 3 stages)
    constexpr int SM_AV = (4 * 128 * 40 + 4 * 32 * 72) * 2;    // 59392 (NN 128x64x32, 4 stages)

    // 0) fp32 -> fp16 converts
    {
        int n4;
        n4 = PB * PN * PC / 4;  f2h<<<(n4 + 255) / 256, 256>>>(x, xh, n4);
        n4 = 3 * PC * PC / 4;   f2h<<<(n4 + 255) / 256, 256>>>(W_qkv, wqh, n4);
        n4 = PC * PC / 4;       f2h<<<(n4 + 255) / 256, 256>>>(W_proj, wph, n4);
    }

    // 1) QKV projection + pack (fp16 out): [4096,768] x [2304,768]^T
    {
        auto kfn = gemm_h<128, 128, 32, 3, true, 2>;
        cudaFuncSetAttribute(kfn, cudaFuncAttributeMaxDynamicSharedMemorySize, SM_A);
        dim3 grid(3 * PC / 128, M / 128, 1);
        kfn<<<grid, 256, SM_A>>>(xh, wqh, nullptr, nullptr, M, 3 * PC, PC,
                                 0, 0, 0, 0, PH, 0, qh, kh, vh);
    }

    // 2) scores: per (b,h) S = q k^T (fp32 out), K=64
    {
        auto kfn = gemm_h<128, 128, 32, 3, true, 0>;
        cudaFuncSetAttribute(kfn, cudaFuncAttributeMaxDynamicSharedMemorySize, SM_A);
        dim3 grid(PN / 128, PN / 128, PB * PH);
        kfn<<<grid, 256, SM_A>>>(qh, kh, s, nullptr, PN, PN, PD,
                                 qkstride, qkstride, (long)PH * sstride, sstride, PH, PN,
                                 nullptr, nullptr, nullptr);
    }

    // 3) fused talking-heads + softmax: fp32 S -> fp16 S2
    {
        cudaFuncSetAttribute(talking_softmax,
                             cudaFuncAttributeMaxDynamicSharedMemorySize, 49152);
        talking_softmax<<<PB * PN, 384, 49152>>>(s, s2, W_l, b_l, W_w, b_w, lamb);
    }

    // 4) O = P @ V: per (b,h) [1024,1024]x[1024,64] -> oh[B,N,C] fp16
    {
        auto kfn = gemm_h<128, 64, 32, 4, false, 1>;
        cudaFuncSetAttribute(kfn, cudaFuncAttributeMaxDynamicSharedMemorySize, SM_AV);
        dim3 grid(PD / 64, PN / 128, PB * PH);
        kfn<<<grid, 256, SM_AV>>>(s2, vh, oh, nullptr, PN, PD, PN,
                                  sstride, qkstride, (long)PN * PC, (long)PD, PH, PC,
                                  nullptr, nullptr, nullptr);
    }

    // 5) output projection + bias: [4096,768] x [768,768]^T -> fp32 d_out
    {
        auto kfn = gemm_h<128, 128, 32, 3, true, 0>;
        cudaFuncSetAttribute(kfn, cudaFuncAttributeMaxDynamicSharedMemorySize, SM_A);
        dim3 grid(PC / 128, M / 128, 1);
        kfn<<<grid, 256, SM_A>>>(oh, wph, out, b_proj, M, PC, PC,
                                 0, 0, 0, 0, PH, PC, nullptr, nullptr, nullptr);
    }
}

// round 8
// speedup vs baseline: 1.5328x; 1.0095x over previous
#include <cuda_runtime.h>
#include <cuda_fp16.h>
#include <math.h>
#include <stdint.h>

// Problem constants (fixed: B=4, N=1024, C=768, H=12, Dh=64)
#define PB 4
#define PN 1024
#define PC 768
#define PH 12
#define PD 64
#define PSCALE 0.125f

// ---------------- scratch (static device arrays; no allocation) ----------------
__device__ __half g_xh[(long)PB * PN * PC];            // 6 MB
__device__ __half g_wqh[(long)3 * PC * PC];            // 3.4 MB
__device__ __half g_wph[(long)PC * PC];                // 1.1 MB
__device__ __half g_qh[(long)PB * PH * PN * PD];       // 6 MB [B,H,N,D]
__device__ __half g_kh[(long)PB * PH * PN * PD];
__device__ __half g_vh[(long)PB * PH * PN * PD];
__device__ float  g_s [(long)PB * PH * PN * PN];       // 192 MB [B,H,N,N] pre-softmax
__device__ __half g_s2[(long)PB * PH * PN * PN];       // 96 MB  post-softmax probs
__device__ __half g_oh[(long)PB * PN * PC];            // 6 MB [B,N,C]

__device__ __forceinline__ uint32_t smem_u32(const void* p) {
    return (uint32_t)__cvta_generic_to_shared(p);
}
__device__ __forceinline__ void cp_async16(uint32_t dst, const void* src) {
    asm volatile("cp.async.cg.shared.global [%0], [%1], 16;" :: "r"(dst), "l"(src));
}
__device__ __forceinline__ void cp_commit() {
    asm volatile("cp.async.commit_group;");
}
template<int N_>
__device__ __forceinline__ void cp_wait() {
    asm volatile("cp.async.wait_group %0;" :: "n"(N_));
}
__device__ __forceinline__ void ldmatrix_x4(uint32_t& r0, uint32_t& r1, uint32_t& r2, uint32_t& r3,
                                            uint32_t addr) {
    asm volatile("ldmatrix.sync.aligned.m8n8.x4.shared.b16 {%0,%1,%2,%3}, [%4];"
                 : "=r"(r0), "=r"(r1), "=r"(r2), "=r"(r3) : "r"(addr));
}
__device__ __forceinline__ void ldmatrix_x2(uint32_t& r0, uint32_t& r1, uint32_t addr) {
    asm volatile("ldmatrix.sync.aligned.m8n8.x2.shared.b16 {%0,%1}, [%2];"
                 : "=r"(r0), "=r"(r1) : "r"(addr));
}
__device__ __forceinline__ void ldmatrix_x2_trans(uint32_t& r0, uint32_t& r1, uint32_t addr) {
    asm volatile("ldmatrix.sync.aligned.m8n8.x2.trans.shared.b16 {%0,%1}, [%2];"
                 : "=r"(r0), "=r"(r1) : "r"(addr));
}
__device__ __forceinline__ void mma_f16(float& c0, float& c1, float& c2, float& c3,
                                        uint32_t a0, uint32_t a1, uint32_t a2, uint32_t a3,
                                        uint32_t b0, uint32_t b1) {
    asm volatile(
        "mma.sync.aligned.m16n8k16.row.col.f32.f16.f16.f32 "
        "{%0,%1,%2,%3}, {%4,%5,%6,%7}, {%8,%9}, {%0,%1,%2,%3};"
        : "+f"(c0), "+f"(c1), "+f"(c2), "+f"(c3)
        : "r"(a0), "r"(a1), "r"(a2), "r"(a3), "r"(b0), "r"(b1));
}

// fast exp for x<=0 (FMA pipe, no MUFU): exp(x) = 2^(x*log2e)
__device__ __forceinline__ float fexp(float x) {
    float y = fmaxf(x * 1.4426950408889634f, -80.0f);
    float t = y + 12582912.0f;               // round-to-nearest-int magic (1.5*2^23)
    int   n = __float_as_int(t) - 0x4B400000;
    float r = y - (t - 12582912.0f);         // r in [-0.5, 0.5]
    float p = 1.3333558e-3f;
    p = fmaf(p, r, 9.6181291e-3f);
    p = fmaf(p, r, 5.5504109e-2f);
    p = fmaf(p, r, 2.4022651e-1f);
    p = fmaf(p, r, 6.9314718e-1f);
    p = fmaf(p, r, 1.0f);
    return __int_as_float(__float_as_int(p) + (n << 23));
}

// ---------------- fp32 -> fp16 convert (elementwise, float4-vectorized) ----------------
__global__ void __launch_bounds__(256)
f2h(const float* __restrict__ s, __half* __restrict__ d, int n4)
{
    int i = blockIdx.x * blockDim.x + threadIdx.x;
    if (i < n4) {
        float4 v = ((const float4*)s)[i];
        ((__half2*)d)[i * 2]     = __floats2half2_rn(v.x, v.y);
        ((__half2*)d)[i * 2 + 1] = __floats2half2_rn(v.z, v.w);
    }
}

// ---------------- fp16 cp.async pipelined tensor-core GEMM ----------------
// A: __half [M,K] row-major (k-contig). B: BNT ? [N,K] : [K,N] __half.
// Batched over blockIdx.z: A += z*sA, B += z*sB, C += (z/CB)*sCb + (z%CB)*sCh (elements).
// OUTM: 0 = fp32 out (+bias), 1 = fp16 out, 2 = qkv-pack fp16 (q scaled).
template<int BM, int BN, int BK, int STAGES, bool BNT, int OUTM>
__global__ void __launch_bounds__(256)
gemm_h(const __half* __restrict__ Ab, const __half* __restrict__ Bb,
       void* __restrict__ Cb, const float* __restrict__ bias,
       int M, int N, int K,
       long sA, long sB, long sCb, long sCh, int CB, int ldc,
       __half* __restrict__ qp, __half* __restrict__ kp, __half* __restrict__ vp)
{
    constexpr int BKP = BK + 8;            // A row stride (halves), 16B-aligned
    constexpr int BNP = BN + 8;            // NN-B row stride (halves), 16B-aligned
    constexpr int WM = 4, WN = 2;
    constexpr int WTM = BM / WM;           // 32
    constexpr int WTN = BN / WN;
    constexpr int MT  = WTM / 16;          // 2
    constexpr int NTt = WTN / 8;
    constexpr int ASTG = BM * BKP;         // halves per A stage
    constexpr int BSTG = BNT ? (BN * BKP) : (BK * BNP);
    // A load geometry: 16B = 8 halves
    constexpr int ATPR  = BK / 8;
    constexpr int ARPP  = 256 / ATPR;
    constexpr int APASS = BM / ARPP;
    // B load geometry
    constexpr int BTPR_NT  = BK / 8;
    constexpr int BRPP_NT  = 256 / BTPR_NT;
    constexpr int BPASS_NT = BN / BRPP_NT;
    constexpr int BTPR_NN  = BN / 8;
    constexpr int BRPP_NN  = 256 / BTPR_NN;
    constexpr int BPASS_NN = (BK + BRPP_NN - 1) / BRPP_NN;

    extern __shared__ __half sm[];
    __half* Asm = sm;
    __half* Bsm = sm + (long)STAGES * ASTG;

    const int z = blockIdx.z;
    const __half* A = Ab + (long)z * sA;
    const __half* B = Bb + (long)z * sB;

    const int tid  = threadIdx.x;
    const int warp = tid >> 5;
    const int lane = tid & 31;
    const int g    = lane >> 2;
    const int c4   = lane & 3;
    const int wm   = warp % WM;
    const int wn   = warp / WM;

    const int m0 = blockIdx.y * BM;
    const int n0 = blockIdx.x * BN;

    float acc[MT][NTt][4];
    #pragma unroll
    for (int i = 0; i < MT; i++)
        #pragma unroll
        for (int j = 0; j < NTt; j++)
            #pragma unroll
            for (int r = 0; r < 4; r++) acc[i][j][r] = 0.0f;

    const int nk = K / BK;

    auto load_stage = [&](int st, int k0) {
        {
            const int r  = tid / ATPR;
            const int kc = (tid % ATPR) * 8;
            #pragma unroll
            for (int p = 0; p < APASS; p++)
                cp_async16(smem_u32(Asm + (long)st * ASTG + (r + p * ARPP) * BKP + kc),
                           A + (long)(m0 + r + p * ARPP) * K + k0 + kc);
        }
        if constexpr (BNT) {
            const int r  = tid / BTPR_NT;
            const int kc = (tid % BTPR_NT) * 8;
            #pragma unroll
            for (int p = 0; p < BPASS_NT; p++)
                cp_async16(smem_u32(Bsm + (long)st * BSTG + (r + p * BRPP_NT) * BKP + kc),
                           B + (long)(n0 + r + p * BRPP_NT) * K + k0 + kc);
        } else {
            const int kr = tid / BTPR_NN;
            const int nc = (tid % BTPR_NN) * 8;
            #pragma unroll
            for (int p = 0; p < BPASS_NN; p++) {
                const int k = kr + p * BRPP_NN;
                if (k < BK)
                    cp_async16(smem_u32(Bsm + (long)st * BSTG + k * BNP + nc),
                               B + (long)(k0 + k) * N + n0 + nc);
            }
        }
    };

    auto compute_stage = [&](int st) {
        const __half* As = Asm + (long)st * ASTG;
        const __half* Bs = Bsm + (long)st * BSTG;
        #pragma unroll
        for (int kk = 0; kk < BK; kk += 16) {
            uint32_t afr[MT][4];
            #pragma unroll
            for (int mt = 0; mt < MT; mt++) {
                const int rbase = wm * WTM + mt * 16;
                uint32_t addr = smem_u32(As + (rbase + (lane & 15)) * BKP + kk + ((lane >> 4) << 3));
                ldmatrix_x4(afr[mt][0], afr[mt][1], afr[mt][2], afr[mt][3], addr);
            }
            uint32_t bfr[NTt][2];
            #pragma unroll
            for (int nt = 0; nt < NTt; nt++) {
                const int nb = wn * WTN + nt * 8;
                if constexpr (BNT) {
                    uint32_t addr = smem_u32(Bs + (nb + (lane & 7)) * BKP + kk + (((lane >> 3) & 1) << 3));
                    ldmatrix_x2(bfr[nt][0], bfr[nt][1], addr);
                } else {
                    uint32_t addr = smem_u32(Bs + (kk + (lane & 15)) * BNP + nb);
                    ldmatrix_x2_trans(bfr[nt][0], bfr[nt][1], addr);
                }
            }
            #pragma unroll
            for (int mt = 0; mt < MT; mt++)
                #pragma unroll
                for (int nt = 0; nt < NTt; nt++)
                    mma_f16(acc[mt][nt][0], acc[mt][nt][1], acc[mt][nt][2], acc[mt][nt][3],
                            afr[mt][0], afr[mt][1], afr[mt][2], afr[mt][3],
                            bfr[nt][0], bfr[nt][1]);
        }
    };

    // ---- pipelined mainloop ----
    #pragma unroll
    for (int s = 0; s < STAGES - 1; s++) {
        if (s < nk) load_stage(s, s * BK);
        cp_commit();
    }
    for (int i = 0; i < nk; i++) {
        cp_wait<STAGES - 2>();
        __syncthreads();
        compute_stage(i % STAGES);
        const int nx = i + STAGES - 1;
        if (nx < nk) load_stage(nx % STAGES, nx * BK);
        cp_commit();
        __syncthreads();
    }

    // ---- epilogue ----
    if constexpr (OUTM == 0) {
        float* C = (float*)Cb + (long)(z / CB) * sCb + (long)(z % CB) * sCh;
        #pragma unroll
        for (int mt = 0; mt < MT; mt++) {
            const int row = m0 + wm * WTM + mt * 16 + g;
            #pragma unroll
            for (int nt = 0; nt < NTt; nt++) {
                const int col = n0 + wn * WTN + nt * 8 + c4 * 2;
                float b0 = 0.0f, b1 = 0.0f;
                if (bias) { b0 = bias[col]; b1 = bias[col + 1]; }
                *(float2*)(C + (long)row * ldc + col) =
                    make_float2(acc[mt][nt][0] + b0, acc[mt][nt][1] + b1);
                *(float2*)(C + (long)(row + 8) * ldc + col) =
                    make_float2(acc[mt][nt][2] + b0, acc[mt][nt][3] + b1);
            }
        }
    } else if constexpr (OUTM == 1) {
        __half* C = (__half*)Cb + (long)(z / CB) * sCb + (long)(z % CB) * sCh;
        #pragma unroll
        for (int mt = 0; mt < MT; mt++) {
            const int row = m0 + wm * WTM + mt * 16 + g;
            #pragma unroll
            for (int nt = 0; nt < NTt; nt++) {
                const int col = n0 + wn * WTN + nt * 8 + c4 * 2;
                *(__half2*)(C + (long)row * ldc + col) =
                    __floats2half2_rn(acc[mt][nt][0], acc[mt][nt][1]);
                *(__half2*)(C + (long)(row + 8) * ldc + col) =
                    __floats2half2_rn(acc[mt][nt][2], acc[mt][nt][3]);
            }
        }
    } else {
        // qkv pack: row in [0,4096) -> (b,n); col in [0,2304) -> (s,h,d)
        #pragma unroll
        for (int mt = 0; mt < MT; mt++) {
            const int row = m0 + wm * WTM + mt * 16 + g;
            const int b = row >> 10;
            const int n = row & 1023;
            #pragma unroll
            for (int nt = 0; nt < NTt; nt++) {
                const int col = n0 + wn * WTN + nt * 8 + c4 * 2;
                const int s  = col / PC;
                const int r2 = col % PC;
                const int h  = r2 >> 6;
                const int d  = r2 & 63;
                __half* dstb = (s == 0) ? qp : (s == 1) ? kp : vp;
                const float sc = (s == 0) ? PSCALE : 1.0f;
                const long base = (((long)(b * PH + h) * PN) + n) * PD + d;
                *(__half2*)(dstb + base) =
                    __floats2half2_rn(acc[mt][nt][0] * sc, acc[mt][nt][1] * sc);
                *(__half2*)(dstb + base + 8L * PD) =
                    __floats2half2_rn(acc[mt][nt][2] * sc, acc[mt][nt][3] * sc);
            }
        }
    }
}

// ---------------- fused talking-heads + softmax (fp32 in, fp16 out) ----------------
__global__ void __launch_bounds__(384)
talking_softmax(const float* __restrict__ S, __half* __restrict__ S2,
                const float* __restrict__ W_l, const float* __restrict__ b_l,
                const float* __restrict__ W_w, const float* __restrict__ b_w,
                const float* __restrict__ lamb)
{
    extern __shared__ float sraw[];
    float (*sbuf)[PN] = (float(*)[PN])sraw;          // [12][1024] = 48 KB

    __shared__ float wl[PH * PH], ww[PH * PH];
    __shared__ float bl[PH], bw[PH], lam[PH];

    const int tid = threadIdx.x;
    const int row = blockIdx.x;
    const int b = row >> 10;
    const int n = row & 1023;

    if (tid < PH * PH) { wl[tid] = W_l[tid]; ww[tid] = W_w[tid]; }
    if (tid < PH)      { bl[tid] = b_l[tid]; bw[tid] = b_w[tid]; lam[tid] = lamb[tid]; }

    for (int t = tid; t < PH * (PN / 4); t += 384) {
        const int h  = t >> 8;
        const int m4 = t & 255;
        const long base = (((long)(b * PH + h) * PN) + n) * PN;
        *(float4*)&sbuf[h][m4 * 4] = *(const float4*)(S + base + m4 * 4);
    }
    __syncthreads();

    // pre-softmax head mix
    for (int m = tid; m < PN; m += 384) {
        float s[PH], o[PH];
        #pragma unroll
        for (int h = 0; h < PH; h++) s[h] = sbuf[h][m];
        #pragma unroll
        for (int gg = 0; gg < PH; gg++) {
            float t = bl[gg];
            #pragma unroll
            for (int h = 0; h < PH; h++) t += wl[gg * PH + h] * s[h];
            o[gg] = t;
        }
        #pragma unroll
        for (int gg = 0; gg < PH; gg++) sbuf[gg][m] = o[gg];
    }
    __syncthreads();

    // softmax per head (warp w -> head w), FMA-pipe exp
    {
        const int w = tid >> 5;
        const int l = tid & 31;
        float mx = -INFINITY;
        for (int m = l; m < PN; m += 32) mx = fmaxf(mx, sbuf[w][m]);
        #pragma unroll
        for (int off = 16; off > 0; off >>= 1)
            mx = fmaxf(mx, __shfl_xor_sync(0xFFFFFFFFu, mx, off));
        float sum = 0.0f;
        for (int m = l; m < PN; m += 32) {
            const float e = fexp(sbuf[w][m] - mx);
            sbuf[w][m] = e;
            sum += e;
        }
        #pragma unroll
        for (int off = 16; off > 0; off >>= 1)
            sum += __shfl_xor_sync(0xFFFFFFFFu, sum, off);
        const float inv = 1.0f / sum;
        for (int m = l; m < PN; m += 32) sbuf[w][m] *= inv;
    }
    __syncthreads();

    // post-softmax head mix + attnscale
    const float attn_d = 1.0f / (float)PN;
    for (int m = tid; m < PN; m += 384) {
        float p[PH], o[PH];
        #pragma unroll
        for (int h = 0; h < PH; h++) p[h] = sbuf[h][m];
        #pragma unroll
        for (int gg = 0; gg < PH; gg++) {
            float a = bw[gg];
            #pragma unroll
            for (int h = 0; h < PH; h++) a += ww[gg * PH + h] * p[h];
            o[gg] = a * (1.0f + lam[gg]) - attn_d * lam[gg];
        }
        #pragma unroll
        for (int gg = 0; gg < PH; gg++) sbuf[gg][m] = o[gg];
    }
    __syncthreads();

    // store post-softmax probs as fp16
    for (int t = tid; t < PH * (PN / 4); t += 384) {
        const int h  = t >> 8;
        const int m4 = t & 255;
        const long base = (((long)(b * PH + h) * PN) + n) * PN;
        float4 v = *(const float4*)&sbuf[h][m4 * 4];
        __half2* dst = (__half2*)(S2 + base + m4 * 4);
        dst[0] = __floats2half2_rn(v.x, v.y);
        dst[1] = __floats2half2_rn(v.z, v.w);
    }
}

// ---------------- launcher ----------------
extern "C" void kernel_launch(void* const* d_in, const int* in_sizes, int n_in,
                              void* d_out, int out_size)
{
    const float* x      = (const float*)d_in[0];
    const float* W_qkv  = (const float*)d_in[1];
    const float* W_proj = (const float*)d_in[2];
    const float* b_proj = (const float*)d_in[3];
    const float* W_l    = (const float*)d_in[4];
    const float* b_l    = (const float*)d_in[5];
    const float* W_w    = (const float*)d_in[6];
    const float* b_w    = (const float*)d_in[7];
    const float* lamb   = (const float*)d_in[8];
    float* out = (float*)d_out;

    __half *xh, *wqh, *wph, *qh, *kh, *vh, *s2, *oh;
    float *s;
    cudaGetSymbolAddress((void**)&xh,  g_xh);
    cudaGetSymbolAddress((void**)&wqh, g_wqh);
    cudaGetSymbolAddress((void**)&wph, g_wph);
    cudaGetSymbolAddress((void**)&qh,  g_qh);
    cudaGetSymbolAddress((void**)&kh,  g_kh);
    cudaGetSymbolAddress((void**)&vh,  g_vh);
    cudaGetSymbolAddress((void**)&s,   g_s);
    cudaGetSymbolAddress((void**)&s2,  g_s2);
    cudaGetSymbolAddress((void**)&oh,  g_oh);

    const int M = PB * PN;                     // 4096
    const long qkstride = (long)PN * PD;       // per (b,h)
    const long sstride  = (long)PN * PN;       // per (b,h)

    // smem sizes per instantiation
    constexpr int SM_A  = (3 * 128 * 40 + 3 * 128 * 40) * 2;   // 61440 (BNT 128x128x32, 3 stages)
    constexpr int SM_AV = (4 * 128 * 40 + 4 * 32 * 72) * 2;    // 59392 (NN 128x64x32, 4 stages)

    // 0) fp32 -> fp16 converts
    {
        int n4;
        n4 = PB * PN * PC / 4;  f2h<<<(n4 + 255) / 256, 256>>>(x, xh, n4);
        n4 = 3 * PC * PC / 4;   f2h<<<(n4 + 255) / 256, 256>>>(W_qkv, wqh, n4);
        n4 = PC * PC / 4;       f2h<<<(n4 + 255) / 256, 256>>>(W_proj, wph, n4);
    }

    // 1) QKV projection + pack (fp16 out): [4096,768] x [2304,768]^T
    {
        auto kfn = gemm_h<128, 128, 32, 3, true, 2>;
        cudaFuncSetAttribute(kfn, cudaFuncAttributeMaxDynamicSharedMemorySize, SM_A);
        dim3 grid(3 * PC / 128, M / 128, 1);
        kfn<<<grid, 256, SM_A>>>(xh, wqh, nullptr, nullptr, M, 3 * PC, PC,
                                 0, 0, 0, 0, PH, 0, qh, kh, vh);
    }

    // 2) scores: per (b,h) S = q k^T (fp32 out), K=64
    {
        auto kfn = gemm_h<128, 128, 32, 3, true, 0>;
        cudaFuncSetAttribute(kfn, cudaFuncAttributeMaxDynamicSharedMemorySize, SM_A);
        dim3 grid(PN / 128, PN / 128, PB * PH);
        kfn<<<grid, 256, SM_A>>>(qh, kh, s, nullptr, PN, PN, PD,
                                 qkstride, qkstride, (long)PH * sstride, sstride, PH, PN,
                                 nullptr, nullptr, nullptr);
    }

    // 3) fused talking-heads + softmax: fp32 S -> fp16 S2
    {
        cudaFuncSetAttribute(talking_softmax,
                             cudaFuncAttributeMaxDynamicSharedMemorySize, 49152);
        talking_softmax<<<PB * PN, 384, 49152>>>(s, s2, W_l, b_l, W_w, b_w, lamb);
    }

    // 4) O = P @ V: per (b,h) [1024,1024]x[1024,64] -> oh[B,N,C] fp16
    {
        auto kfn = gemm_h<128, 64, 32, 4, false, 1>;
        cudaFuncSetAttribute(kfn, cudaFuncAttributeMaxDynamicSharedMemorySize, SM_AV);
        dim3 grid(PD / 64, PN / 128, PB * PH);
        kfn<<<grid, 256, SM_AV>>>(s2, vh, oh, nullptr, PN, PD, PN,
                                  sstride, qkstride, (long)PN * PC, (long)PD, PH, PC,
                                  nullptr, nullptr, nullptr);
    }

    // 5) output projection + bias: [4096,768] x [768,768]^T -> fp32 d_out
    {
        auto kfn = gemm_h<128, 128, 32, 3, true, 0>;
        cudaFuncSetAttribute(kfn, cudaFuncAttributeMaxDynamicSharedMemorySize, SM_A);
        dim3 grid(PC / 128, M / 128, 1);
        kfn<<<grid, 256, SM_A>>>(oh, wph, out, b_proj, M, PC, PC,
                                 0, 0, 0, 0, PH, PC, nullptr, nullptr, nullptr);
    }
}

// round 10
// speedup vs baseline: 7.1005x; 4.6324x over previous
#include <cuda_runtime.h>
#include <cuda_fp16.h>
#include <math.h>
#include <stdint.h>

#define PB 4
#define PN 1024
#define PC 768
#define PH 12
#define PD 64
#define PSCALE 0.125f

// ---------------- scratch ----------------
__device__ __half g_xh[(long)PB * PN * PC];
__device__ __half g_wqh[(long)3 * PC * PC];
__device__ __half g_wph[(long)PC * PC];
__device__ __half g_qh[(long)PB * PH * PN * PD];
__device__ __half g_kh[(long)PB * PH * PN * PD];
__device__ __half g_vh[(long)PB * PH * PN * PD];
__device__ __half g_e [(long)PB * PH * PN * PN];   // 100 MB unnormalized exp scores
__device__ float  g_rs[(long)PB * PH * PN];        // row sums
__device__ __half g_oh[(long)PB * PN * PC];

__device__ __forceinline__ uint32_t smem_u32(const void* p) {
    return (uint32_t)__cvta_generic_to_shared(p);
}
__device__ __forceinline__ void cp_async16(uint32_t dst, const void* src) {
    asm volatile("cp.async.cg.shared.global [%0], [%1], 16;" :: "r"(dst), "l"(src));
}
__device__ __forceinline__ void cp_commit() { asm volatile("cp.async.commit_group;"); }
template<int N_> __device__ __forceinline__ void cp_wait() {
    asm volatile("cp.async.wait_group %0;" :: "n"(N_));
}
__device__ __forceinline__ void ldmx4(uint32_t& r0, uint32_t& r1, uint32_t& r2, uint32_t& r3, uint32_t a) {
    asm volatile("ldmatrix.sync.aligned.m8n8.x4.shared.b16 {%0,%1,%2,%3}, [%4];"
                 : "=r"(r0), "=r"(r1), "=r"(r2), "=r"(r3) : "r"(a));
}
__device__ __forceinline__ void ldmx2(uint32_t& r0, uint32_t& r1, uint32_t a) {
    asm volatile("ldmatrix.sync.aligned.m8n8.x2.shared.b16 {%0,%1}, [%2];"
                 : "=r"(r0), "=r"(r1) : "r"(a));
}
__device__ __forceinline__ void ldmx2t(uint32_t& r0, uint32_t& r1, uint32_t a) {
    asm volatile("ldmatrix.sync.aligned.m8n8.x2.trans.shared.b16 {%0,%1}, [%2];"
                 : "=r"(r0), "=r"(r1) : "r"(a));
}
__device__ __forceinline__ void mma_f16(float& c0, float& c1, float& c2, float& c3,
                                        uint32_t a0, uint32_t a1, uint32_t a2, uint32_t a3,
                                        uint32_t b0, uint32_t b1) {
    asm volatile(
        "mma.sync.aligned.m16n8k16.row.col.f32.f16.f16.f32 "
        "{%0,%1,%2,%3}, {%4,%5,%6,%7}, {%8,%9}, {%0,%1,%2,%3};"
        : "+f"(c0), "+f"(c1), "+f"(c2), "+f"(c3)
        : "r"(a0), "r"(a1), "r"(a2), "r"(a3), "r"(b0), "r"(b1));
}
__device__ __forceinline__ float fexp(float x) {   // FMA-pipe exp
    float y = fmaxf(x * 1.4426950408889634f, -80.0f);
    float t = y + 12582912.0f;
    int   n = __float_as_int(t) - 0x4B400000;
    float r = y - (t - 12582912.0f);
    float p = 1.3333558e-3f;
    p = fmaf(p, r, 9.6181291e-3f);
    p = fmaf(p, r, 5.5504109e-2f);
    p = fmaf(p, r, 2.4022651e-1f);
    p = fmaf(p, r, 6.9314718e-1f);
    p = fmaf(p, r, 1.0f);
    return __int_as_float(__float_as_int(p) + (n << 23));
}

__global__ void __launch_bounds__(256)
f2h(const float* __restrict__ s, __half* __restrict__ d, int n4)
{
    int i = blockIdx.x * blockDim.x + threadIdx.x;
    if (i < n4) {
        float4 v = ((const float4*)s)[i];
        ((__half2*)d)[i * 2]     = __floats2half2_rn(v.x, v.y);
        ((__half2*)d)[i * 2 + 1] = __floats2half2_rn(v.z, v.w);
    }
}

// ---------------- fp16 cp.async GEMM, B^T layout (QKV + proj) ----------------
// OUTM: 0 = fp32 out (+bias), 2 = qkv-pack fp16 (q scaled)
template<int BM, int BN, int BK, int STAGES, int OUTM>
__global__ void __launch_bounds__(256)
gemm_h(const __half* __restrict__ A, const __half* __restrict__ B,
       void* __restrict__ Cb, const float* __restrict__ bias,
       int M, int N, int K, int ldc,
       __half* __restrict__ qp, __half* __restrict__ kp, __half* __restrict__ vp)
{
    constexpr int BKP = BK + 8;
    constexpr int WM = 4, WN = 2;
    constexpr int WTM = BM / WM, WTN = BN / WN;
    constexpr int MT = WTM / 16, NTt = WTN / 8;
    constexpr int ASTG = BM * BKP, BSTG = BN * BKP;
    constexpr int TPR = BK / 8, RPP = 256 / TPR;
    constexpr int APASS = BM / RPP, BPASS = BN / RPP;

    extern __shared__ __half sm[];
    __half* Asm = sm;
    __half* Bsm = sm + (long)STAGES * ASTG;

    const int tid = threadIdx.x, warp = tid >> 5, lane = tid & 31;
    const int g = lane >> 2, c4 = lane & 3;
    const int wm = warp % WM, wn = warp / WM;
    const int m0 = blockIdx.y * BM, n0 = blockIdx.x * BN;

    float acc[MT][NTt][4];
    #pragma unroll
    for (int i = 0; i < MT; i++)
        #pragma unroll
        for (int j = 0; j < NTt; j++)
            #pragma unroll
            for (int r = 0; r < 4; r++) acc[i][j][r] = 0.0f;

    const int nk = K / BK;
    auto load_stage = [&](int st, int k0) {
        const int r = tid / TPR, kc = (tid % TPR) * 8;
        #pragma unroll
        for (int p = 0; p < APASS; p++)
            cp_async16(smem_u32(Asm + (long)st * ASTG + (r + p * RPP) * BKP + kc),
                       A + (long)(m0 + r + p * RPP) * K + k0 + kc);
        #pragma unroll
        for (int p = 0; p < BPASS; p++)
            cp_async16(smem_u32(Bsm + (long)st * BSTG + (r + p * RPP) * BKP + kc),
                       B + (long)(n0 + r + p * RPP) * K + k0 + kc);
    };
    auto compute_stage = [&](int st) {
        const __half* As = Asm + (long)st * ASTG;
        const __half* Bs = Bsm + (long)st * BSTG;
        #pragma unroll
        for (int kk = 0; kk < BK; kk += 16) {
            uint32_t afr[MT][4];
            #pragma unroll
            for (int mt = 0; mt < MT; mt++)
                ldmx4(afr[mt][0], afr[mt][1], afr[mt][2], afr[mt][3],
                      smem_u32(As + (wm * WTM + mt * 16 + (lane & 15)) * BKP + kk + ((lane >> 4) << 3)));
            uint32_t bfr[NTt][2];
            #pragma unroll
            for (int nt = 0; nt < NTt; nt++)
                ldmx2(bfr[nt][0], bfr[nt][1],
                      smem_u32(Bs + (wn * WTN + nt * 8 + (lane & 7)) * BKP + kk + (((lane >> 3) & 1) << 3)));
            #pragma unroll
            for (int mt = 0; mt < MT; mt++)
                #pragma unroll
                for (int nt = 0; nt < NTt; nt++)
                    mma_f16(acc[mt][nt][0], acc[mt][nt][1], acc[mt][nt][2], acc[mt][nt][3],
                            afr[mt][0], afr[mt][1], afr[mt][2], afr[mt][3],
                            bfr[nt][0], bfr[nt][1]);
        }
    };

    #pragma unroll
    for (int s = 0; s < STAGES - 1; s++) {
        if (s < nk) load_stage(s, s * BK);
        cp_commit();
    }
    for (int i = 0; i < nk; i++) {
        cp_wait<STAGES - 2>();
        __syncthreads();
        compute_stage(i % STAGES);
        const int nx = i + STAGES - 1;
        if (nx < nk) load_stage(nx % STAGES, nx * BK);
        cp_commit();
        __syncthreads();
    }

    if constexpr (OUTM == 0) {
        float* C = (float*)Cb;
        #pragma unroll
        for (int mt = 0; mt < MT; mt++) {
            const int row = m0 + wm * WTM + mt * 16 + g;
            #pragma unroll
            for (int nt = 0; nt < NTt; nt++) {
                const int col = n0 + wn * WTN + nt * 8 + c4 * 2;
                float b0 = 0.0f, b1 = 0.0f;
                if (bias) { b0 = bias[col]; b1 = bias[col + 1]; }
                *(float2*)(C + (long)row * ldc + col) =
                    make_float2(acc[mt][nt][0] + b0, acc[mt][nt][1] + b1);
                *(float2*)(C + (long)(row + 8) * ldc + col) =
                    make_float2(acc[mt][nt][2] + b0, acc[mt][nt][3] + b1);
            }
        }
    } else {
        #pragma unroll
        for (int mt = 0; mt < MT; mt++) {
            const int row = m0 + wm * WTM + mt * 16 + g;
            const int b = row >> 10, n = row & 1023;
            #pragma unroll
            for (int nt = 0; nt < NTt; nt++) {
                const int col = n0 + wn * WTN + nt * 8 + c4 * 2;
                const int s = col / PC, r2 = col % PC;
                const int h = r2 >> 6, d = r2 & 63;
                __half* dstb = (s == 0) ? qp : (s == 1) ? kp : vp;
                const float sc = (s == 0) ? PSCALE : 1.0f;
                const long base = (((long)(b * PH + h) << 10) + n) * PD + d;
                *(__half2*)(dstb + base) = __floats2half2_rn(acc[mt][nt][0] * sc, acc[mt][nt][1] * sc);
                *(__half2*)(dstb + base + 8L * PD) = __floats2half2_rn(acc[mt][nt][2] * sc, acc[mt][nt][3] * sc);
            }
        }
    }
}

// ---------------- Stage 1: QK + pre-mix + exp + row sums ----------------
// CTA = (n-tile 32, b), 256 threads. smem: q[12][32][72], k double, e-stage [12][32][32]
#define S1_K0 55296
#define S1_E  165888
#define S1_SM 190464

__global__ void __launch_bounds__(256)
qk_exp(const __half* __restrict__ qh, const __half* __restrict__ kh,
       __half* __restrict__ eG, float* __restrict__ rsG,
       const float* __restrict__ W_l, const float* __restrict__ b_l)
{
    extern __shared__ char dyn[];
    __half* qT = (__half*)dyn;
    __half* kB[2] = { (__half*)(dyn + S1_K0), (__half*)(dyn + 2 * S1_K0) };
    __half* eS = (__half*)(dyn + S1_E);
    __shared__ float wl[144], bls[12];
    __shared__ float rs[12][32];

    const int tid = threadIdx.x, warp = tid >> 5, lane = tid & 31;
    const int c4 = lane & 3, r8 = lane >> 2;
    const int wA = warp & 3, wN = warp >> 2;
    const int n0 = blockIdx.x * 32, b = blockIdx.y;

    if (tid < 144) wl[tid] = W_l[tid];
    if (tid < 12)  bls[tid] = b_l[tid];
    for (int t = tid; t < 384; t += 256) ((float*)rs)[t] = 0.0f;   // FIXED: full 384-entry init

    #pragma unroll
    for (int it = 0; it < 12; it++) {
        int c = it * 256 + tid, h = c >> 8, rr = (c >> 3) & 31, cc = (c & 7) * 8;
        cp_async16(smem_u32(qT + (h * 32 + rr) * 72 + cc),
                   qh + (((long)(b * PH + h) << 10) + n0 + rr) * PD + cc);
    }
    cp_commit();

    auto loadk = [&](int mt, __half* buf) {
        #pragma unroll
        for (int it = 0; it < 12; it++) {
            int c = it * 256 + tid, h = c >> 8, rr = (c >> 3) & 31, cc = (c & 7) * 8;
            cp_async16(smem_u32(buf + (h * 32 + rr) * 72 + cc),
                       kh + (((long)(b * PH + h) << 10) + mt * 32 + rr) * PD + cc);
        }
    };
    loadk(0, kB[0]); cp_commit();

    float ps[12][2];
    #pragma unroll
    for (int g = 0; g < 12; g++) { ps[g][0] = 0.0f; ps[g][1] = 0.0f; }

    for (int mt = 0; mt < 32; mt++) {
        __half* cur = kB[mt & 1];
        if (mt + 1 < 32) { loadk(mt + 1, kB[(mt + 1) & 1]); cp_commit(); cp_wait<1>(); }
        else             { cp_wait<0>(); }
        __syncthreads();

        float acc[12][4];
        #pragma unroll
        for (int h = 0; h < 12; h++)
            #pragma unroll
            for (int r = 0; r < 4; r++) acc[h][r] = 0.0f;
        #pragma unroll
        for (int h = 0; h < 12; h++) {
            #pragma unroll
            for (int kc = 0; kc < 4; kc++) {
                uint32_t a0, a1, a2, a3, b0, b1;
                ldmx4(a0, a1, a2, a3,
                      smem_u32(qT + (h * 32 + wN * 16 + (lane & 15)) * 72 + kc * 16 + ((lane >> 4) << 3)));
                ldmx2(b0, b1,
                      smem_u32(cur + (h * 32 + wA * 8 + (lane & 7)) * 72 + kc * 16 + (((lane >> 3) & 1) << 3)));
                mma_f16(acc[h][0], acc[h][1], acc[h][2], acc[h][3], a0, a1, a2, a3, b0, b1);
            }
        }
        #pragma unroll
        for (int g = 0; g < 12; g++) {
            float t0 = bls[g], t1 = t0, t2 = t0, t3 = t0;
            #pragma unroll
            for (int h = 0; h < 12; h++) {
                const float w = wl[g * 12 + h];
                t0 = fmaf(w, acc[h][0], t0); t1 = fmaf(w, acc[h][1], t1);
                t2 = fmaf(w, acc[h][2], t2); t3 = fmaf(w, acc[h][3], t3);
            }
            const float e0 = fexp(t0), e1 = fexp(t1), e2 = fexp(t2), e3 = fexp(t3);
            ps[g][0] += e0 + e1; ps[g][1] += e2 + e3;
            const int mcol = wA * 8 + c4 * 2;
            *(__half2*)(eS + (g * 32 + wN * 16 + r8) * 32 + mcol)     = __floats2half2_rn(e0, e1);
            *(__half2*)(eS + (g * 32 + wN * 16 + r8 + 8) * 32 + mcol) = __floats2half2_rn(e2, e3);
        }
        __syncthreads();
        #pragma unroll
        for (int j = 0; j < 6; j++) {
            int c = tid + j * 256, h = c >> 7, nn = (c >> 2) & 31, q4 = c & 3;
            float4 v = *(float4*)(eS + (h * 32 + nn) * 32 + q4 * 8);
            *(float4*)(eG + ((long)(b * PH + h) << 20) + ((long)(n0 + nn) << 10) + mt * 32 + q4 * 8) = v;
        }
    }
    #pragma unroll
    for (int g = 0; g < 12; g++)
        #pragma unroll
        for (int q = 0; q < 2; q++) {
            ps[g][q] += __shfl_xor_sync(0xFFFFFFFFu, ps[g][q], 1);
            ps[g][q] += __shfl_xor_sync(0xFFFFFFFFu, ps[g][q], 2);
        }
    __syncthreads();
    if (c4 == 0) {
        #pragma unroll
        for (int g = 0; g < 12; g++) {
            atomicAdd(&rs[g][wN * 16 + r8],     ps[g][0]);
            atomicAdd(&rs[g][wN * 16 + r8 + 8], ps[g][1]);
        }
    }
    __syncthreads();
    for (int t = tid; t < 384; t += 256) {                          // FIXED: full 384-entry writeback
        int h = t >> 5, nn = t & 31;
        rsG[((long)(b * PH + h) << 10) + n0 + nn] = rs[h][nn];
    }
}

// ---------------- Stage 2: normalize + post-mix + attnscale + PV ----------------
// CTA = (n-tile 16, b), 256 threads. smem: e double [12][16][40], V double [12][32][72]
#define S2_E  15360
#define S2_V0 30720
#define S2_V  55296
#define S2_SM 141312

__global__ void __launch_bounds__(256)
mix_pv(const __half* __restrict__ eG, const __half* __restrict__ vh,
       const float* __restrict__ rsG, __half* __restrict__ oh,
       const float* __restrict__ W_w, const float* __restrict__ b_w,
       const float* __restrict__ lamb)
{
    extern __shared__ char dyn[];
    __half* eB[2] = { (__half*)dyn, (__half*)(dyn + S2_E) };
    __half* vB[2] = { (__half*)(dyn + S2_V0), (__half*)(dyn + S2_V0 + S2_V) };
    __shared__ float wp[144], cg[12], invS[12][16];

    const int tid = threadIdx.x, w = tid >> 5, lane = tid & 31;
    const int c4 = lane & 3, r8 = lane >> 2;
    const int n0 = blockIdx.x * 16, b = blockIdx.y;

    if (tid < 144) wp[tid] = W_w[tid] * (1.0f + lamb[tid / 12]);
    if (tid < 12) { const float ad = 1.0f / 1024.0f; cg[tid] = ad + (b_w[tid] - ad) * (1.0f + lamb[tid]); }
    if (tid < 192) {
        int h = tid >> 4, nn = tid & 15;
        invS[h][nn] = 1.0f / rsG[((long)(b * PH + h) << 10) + n0 + nn];
    }

    auto loadE = [&](int mt, __half* buf) {
        #pragma unroll
        for (int j = 0; j < 3; j++) {
            int c = tid + j * 256, h = c >> 6, nn = (c >> 2) & 15, q4 = c & 3;
            cp_async16(smem_u32(buf + (h * 16 + nn) * 40 + q4 * 8),
                       eG + ((long)(b * PH + h) << 20) + ((long)(n0 + nn) << 10) + mt * 32 + q4 * 8);
        }
    };
    auto loadV = [&](int mt, __half* buf) {
        #pragma unroll
        for (int it = 0; it < 12; it++) {
            int c = it * 256 + tid, h = c >> 8, rr = (c >> 3) & 31, cc = (c & 7) * 8;
            cp_async16(smem_u32(buf + (h * 32 + rr) * 72 + cc),
                       vh + (((long)(b * PH + h) << 10) + mt * 32 + rr) * PD + cc);
        }
    };

    float acc[12][4];
    #pragma unroll
    for (int h = 0; h < 12; h++)
        #pragma unroll
        for (int r = 0; r < 4; r++) acc[h][r] = 0.0f;

    loadE(0, eB[0]); loadV(0, vB[0]); cp_commit();

    for (int mt = 0; mt < 32; mt++) {
        __half* ec = eB[mt & 1];
        __half* vc = vB[mt & 1];
        if (mt + 1 < 32) { loadE(mt + 1, eB[(mt + 1) & 1]); loadV(mt + 1, vB[(mt + 1) & 1]); cp_commit(); cp_wait<1>(); }
        else             { cp_wait<0>(); }
        __syncthreads();

        float Areg[2][12];
        #pragma unroll
        for (int p2 = 0; p2 < 2; p2++) {
            const int p = tid + p2 * 256, nn = p >> 5, m = p & 31;
            float f[12];
            #pragma unroll
            for (int h = 0; h < 12; h++)
                f[h] = __half2float(ec[(h * 16 + nn) * 40 + m]) * invS[h][nn];
            #pragma unroll
            for (int g = 0; g < 12; g++) {
                float a = cg[g];
                #pragma unroll
                for (int h = 0; h < 12; h++) a = fmaf(wp[g * 12 + h], f[h], a);
                Areg[p2][g] = a;
            }
        }
        __syncthreads();
        #pragma unroll
        for (int p2 = 0; p2 < 2; p2++) {
            const int p = tid + p2 * 256, nn = p >> 5, m = p & 31;
            #pragma unroll
            for (int g = 0; g < 12; g++)
                ec[(g * 16 + nn) * 40 + m] = __float2half_rn(Areg[p2][g]);
        }
        __syncthreads();

        #pragma unroll
        for (int h = 0; h < 12; h++) {
            #pragma unroll
            for (int kc = 0; kc < 2; kc++) {
                uint32_t a0, a1, a2, a3, b0, b1;
                ldmx4(a0, a1, a2, a3,
                      smem_u32(ec + (h * 16 + (lane & 15)) * 40 + kc * 16 + ((lane >> 4) << 3)));
                ldmx2t(b0, b1,
                       smem_u32(vc + (h * 32 + kc * 16 + (lane & 15)) * 72 + w * 8));
                mma_f16(acc[h][0], acc[h][1], acc[h][2], acc[h][3], a0, a1, a2, a3, b0, b1);
            }
        }
        __syncthreads();
    }

    #pragma unroll
    for (int h = 0; h < 12; h++) {
        const long base = ((long)((b << 10) + n0 + r8)) * PC + h * 64 + w * 8 + c4 * 2;
        *(__half2*)(oh + base)             = __floats2half2_rn(acc[h][0], acc[h][1]);
        *(__half2*)(oh + base + 8L * PC)   = __floats2half2_rn(acc[h][2], acc[h][3]);
    }
}

// ---------------- launcher ----------------
extern "C" void kernel_launch(void* const* d_in, const int* in_sizes, int n_in,
                              void* d_out, int out_size)
{
    const float* x      = (const float*)d_in[0];
    const float* W_qkv  = (const float*)d_in[1];
    const float* W_proj = (const float*)d_in[2];
    const float* b_proj = (const float*)d_in[3];
    const float* W_l    = (const float*)d_in[4];
    const float* b_l    = (const float*)d_in[5];
    const float* W_w    = (const float*)d_in[6];
    const float* b_w    = (const float*)d_in[7];
    const float* lamb   = (const float*)d_in[8];
    float* out = (float*)d_out;

    __half *xh, *wqh, *wph, *qh, *kh, *vh, *e, *oh;
    float *rs;
    cudaGetSymbolAddress((void**)&xh,  g_xh);
    cudaGetSymbolAddress((void**)&wqh, g_wqh);
    cudaGetSymbolAddress((void**)&wph, g_wph);
    cudaGetSymbolAddress((void**)&qh,  g_qh);
    cudaGetSymbolAddress((void**)&kh,  g_kh);
    cudaGetSymbolAddress((void**)&vh,  g_vh);
    cudaGetSymbolAddress((void**)&e,   g_e);
    cudaGetSymbolAddress((void**)&rs,  g_rs);
    cudaGetSymbolAddress((void**)&oh,  g_oh);

    const int M = PB * PN;
    constexpr int SM_G = (3 * 128 * 40 + 3 * 128 * 40) * 2;   // 61440

    {   int n4;
        n4 = PB * PN * PC / 4;  f2h<<<(n4 + 255) / 256, 256>>>(x, xh, n4);
        n4 = 3 * PC * PC / 4;   f2h<<<(n4 + 255) / 256, 256>>>(W_qkv, wqh, n4);
        n4 = PC * PC / 4;       f2h<<<(n4 + 255) / 256, 256>>>(W_proj, wph, n4);
    }
    {   auto kfn = gemm_h<128, 128, 32, 3, 2>;
        cudaFuncSetAttribute(kfn, cudaFuncAttributeMaxDynamicSharedMemorySize, SM_G);
        dim3 grid(3 * PC / 128, M / 128, 1);
        kfn<<<grid, 256, SM_G>>>(xh, wqh, nullptr, nullptr, M, 3 * PC, PC, 0, qh, kh, vh);
    }
    {   cudaFuncSetAttribute(qk_exp, cudaFuncAttributeMaxDynamicSharedMemorySize, S1_SM);
        dim3 grid(PN / 32, PB, 1);
        qk_exp<<<grid, 256, S1_SM>>>(qh, kh, e, rs, W_l, b_l);
    }
    {   cudaFuncSetAttribute(mix_pv, cudaFuncAttributeMaxDynamicSharedMemorySize, S2_SM);
        dim3 grid(PN / 16, PB, 1);
        mix_pv<<<grid, 256, S2_SM>>>(e, vh, rs, oh, W_w, b_w, lamb);
    }
    {   auto kfn = gemm_h<128, 128, 32, 3, 0>;
        cudaFuncSetAttribute(kfn, cudaFuncAttributeMaxDynamicSharedMemorySize, SM_G);
        dim3 grid(PC / 128, M / 128, 1);
        kfn<<<grid, 256, SM_G>>>(oh, wph, out, b_proj, M, PC, PC, PC, nullptr, nullptr, nullptr);
    }
}

// round 11
// speedup vs baseline: 7.5609x; 1.0648x over previous
#include <cuda_runtime.h>
#include <cuda_fp16.h>
#include <math.h>
#include <stdint.h>

#define PB 4
#define PN 1024
#define PC 768
#define PH 12
#define PD 64
#define PSCALE 0.125f

// ---------------- scratch ----------------
__device__ __half g_xh[(long)PB * PN * PC];
__device__ __half g_wqh[(long)3 * PC * PC];
__device__ __half g_wph[(long)PC * PC];
__device__ __half g_qh[(long)PB * PH * PN * PD];
__device__ __half g_kh[(long)PB * PH * PN * PD];
__device__ __half g_vh[(long)PB * PH * PN * PD];
__device__ __half g_e [(long)PB * PH * PN * PN];   // 100 MB unnormalized exp scores
__device__ float  g_rs[(long)PB * PH * PN];        // row sums
__device__ __half g_oh[(long)PB * PN * PC];

__device__ __forceinline__ uint32_t smem_u32(const void* p) {
    return (uint32_t)__cvta_generic_to_shared(p);
}
__device__ __forceinline__ void cp_async16(uint32_t dst, const void* src) {
    asm volatile("cp.async.cg.shared.global [%0], [%1], 16;" :: "r"(dst), "l"(src));
}
__device__ __forceinline__ void cp_commit() { asm volatile("cp.async.commit_group;"); }
template<int N_> __device__ __forceinline__ void cp_wait() {
    asm volatile("cp.async.wait_group %0;" :: "n"(N_));
}
__device__ __forceinline__ void ldmx4(uint32_t& r0, uint32_t& r1, uint32_t& r2, uint32_t& r3, uint32_t a) {
    asm volatile("ldmatrix.sync.aligned.m8n8.x4.shared.b16 {%0,%1,%2,%3}, [%4];"
                 : "=r"(r0), "=r"(r1), "=r"(r2), "=r"(r3) : "r"(a));
}
__device__ __forceinline__ void ldmx2(uint32_t& r0, uint32_t& r1, uint32_t a) {
    asm volatile("ldmatrix.sync.aligned.m8n8.x2.shared.b16 {%0,%1}, [%2];"
                 : "=r"(r0), "=r"(r1) : "r"(a));
}
__device__ __forceinline__ void ldmx2t(uint32_t& r0, uint32_t& r1, uint32_t a) {
    asm volatile("ldmatrix.sync.aligned.m8n8.x2.trans.shared.b16 {%0,%1}, [%2];"
                 : "=r"(r0), "=r"(r1) : "r"(a));
}
__device__ __forceinline__ void mma_f16(float& c0, float& c1, float& c2, float& c3,
                                        uint32_t a0, uint32_t a1, uint32_t a2, uint32_t a3,
                                        uint32_t b0, uint32_t b1) {
    asm volatile(
        "mma.sync.aligned.m16n8k16.row.col.f32.f16.f16.f32 "
        "{%0,%1,%2,%3}, {%4,%5,%6,%7}, {%8,%9}, {%0,%1,%2,%3};"
        : "+f"(c0), "+f"(c1), "+f"(c2), "+f"(c3)
        : "r"(a0), "r"(a1), "r"(a2), "r"(a3), "r"(b0), "r"(b1));
}
__device__ __forceinline__ float fexp(float x) {   // FMA-pipe exp
    float y = fmaxf(x * 1.4426950408889634f, -80.0f);
    float t = y + 12582912.0f;
    int   n = __float_as_int(t) - 0x4B400000;
    float r = y - (t - 12582912.0f);
    float p = 1.3333558e-3f;
    p = fmaf(p, r, 9.6181291e-3f);
    p = fmaf(p, r, 5.5504109e-2f);
    p = fmaf(p, r, 2.4022651e-1f);
    p = fmaf(p, r, 6.9314718e-1f);
    p = fmaf(p, r, 1.0f);
    return __int_as_float(__float_as_int(p) + (n << 23));
}

// ---------------- fused fp32 -> fp16 converts (x, W_qkv, W_proj) ----------------
#define N4_X  (PB * PN * PC / 4)
#define N4_WQ (3 * PC * PC / 4)
#define N4_WP (PC * PC / 4)

__global__ void __launch_bounds__(256)
f2h_all(const float* __restrict__ x, const float* __restrict__ wq,
        const float* __restrict__ wp,
        __half* __restrict__ xh, __half* __restrict__ wqh, __half* __restrict__ wph)
{
    int i = blockIdx.x * blockDim.x + threadIdx.x;
    const float* s; __half* d; int j;
    if (i < N4_X)                 { s = x;  d = xh;  j = i; }
    else if (i < N4_X + N4_WQ)    { s = wq; d = wqh; j = i - N4_X; }
    else if (i < N4_X + N4_WQ + N4_WP) { s = wp; d = wph; j = i - N4_X - N4_WQ; }
    else return;
    float4 v = ((const float4*)s)[j];
    ((__half2*)d)[j * 2]     = __floats2half2_rn(v.x, v.y);
    ((__half2*)d)[j * 2 + 1] = __floats2half2_rn(v.z, v.w);
}

// ---------------- fp16 cp.async GEMM, B^T layout (QKV + proj) ----------------
// OUTM: 0 = fp32 out (+bias), 2 = qkv-pack fp16 (q scaled)
template<int BM, int BN, int BK, int STAGES, int OUTM>
__global__ void __launch_bounds__(256)
gemm_h(const __half* __restrict__ A, const __half* __restrict__ B,
       void* __restrict__ Cb, const float* __restrict__ bias,
       int M, int N, int K, int ldc,
       __half* __restrict__ qp, __half* __restrict__ kp, __half* __restrict__ vp)
{
    constexpr int BKP = BK + 8;
    constexpr int WM = 4, WN = 2;
    constexpr int WTM = BM / WM, WTN = BN / WN;
    constexpr int MT = WTM / 16, NTt = WTN / 8;
    constexpr int ASTG = BM * BKP, BSTG = BN * BKP;
    constexpr int TPR = BK / 8, RPP = 256 / TPR;
    constexpr int APASS = BM / RPP, BPASS = BN / RPP;

    extern __shared__ __half sm[];
    __half* Asm = sm;
    __half* Bsm = sm + (long)STAGES * ASTG;

    const int tid = threadIdx.x, warp = tid >> 5, lane = tid & 31;
    const int g = lane >> 2, c4 = lane & 3;
    const int wm = warp % WM, wn = warp / WM;
    const int m0 = blockIdx.y * BM, n0 = blockIdx.x * BN;

    float acc[MT][NTt][4];
    #pragma unroll
    for (int i = 0; i < MT; i++)
        #pragma unroll
        for (int j = 0; j < NTt; j++)
            #pragma unroll
            for (int r = 0; r < 4; r++) acc[i][j][r] = 0.0f;

    const int nk = K / BK;
    auto load_stage = [&](int st, int k0) {
        const int r = tid / TPR, kc = (tid % TPR) * 8;
        #pragma unroll
        for (int p = 0; p < APASS; p++)
            cp_async16(smem_u32(Asm + (long)st * ASTG + (r + p * RPP) * BKP + kc),
                       A + (long)(m0 + r + p * RPP) * K + k0 + kc);
        #pragma unroll
        for (int p = 0; p < BPASS; p++)
            cp_async16(smem_u32(Bsm + (long)st * BSTG + (r + p * RPP) * BKP + kc),
                       B + (long)(n0 + r + p * RPP) * K + k0 + kc);
    };
    auto compute_stage = [&](int st) {
        const __half* As = Asm + (long)st * ASTG;
        const __half* Bs = Bsm + (long)st * BSTG;
        #pragma unroll
        for (int kk = 0; kk < BK; kk += 16) {
            uint32_t afr[MT][4];
            #pragma unroll
            for (int mt = 0; mt < MT; mt++)
                ldmx4(afr[mt][0], afr[mt][1], afr[mt][2], afr[mt][3],
                      smem_u32(As + (wm * WTM + mt * 16 + (lane & 15)) * BKP + kk + ((lane >> 4) << 3)));
            uint32_t bfr[NTt][2];
            #pragma unroll
            for (int nt = 0; nt < NTt; nt++)
                ldmx2(bfr[nt][0], bfr[nt][1],
                      smem_u32(Bs + (wn * WTN + nt * 8 + (lane & 7)) * BKP + kk + (((lane >> 3) & 1) << 3)));
            #pragma unroll
            for (int mt = 0; mt < MT; mt++)
                #pragma unroll
                for (int nt = 0; nt < NTt; nt++)
                    mma_f16(acc[mt][nt][0], acc[mt][nt][1], acc[mt][nt][2], acc[mt][nt][3],
                            afr[mt][0], afr[mt][1], afr[mt][2], afr[mt][3],
                            bfr[nt][0], bfr[nt][1]);
        }
    };

    #pragma unroll
    for (int s = 0; s < STAGES - 1; s++) {
        if (s < nk) load_stage(s, s * BK);
        cp_commit();
    }
    for (int i = 0; i < nk; i++) {
        cp_wait<STAGES - 2>();
        __syncthreads();
        compute_stage(i % STAGES);
        const int nx = i + STAGES - 1;
        if (nx < nk) load_stage(nx % STAGES, nx * BK);
        cp_commit();
        __syncthreads();
    }

    if constexpr (OUTM == 0) {
        float* C = (float*)Cb;
        #pragma unroll
        for (int mt = 0; mt < MT; mt++) {
            const int row = m0 + wm * WTM + mt * 16 + g;
            #pragma unroll
            for (int nt = 0; nt < NTt; nt++) {
                const int col = n0 + wn * WTN + nt * 8 + c4 * 2;
                float b0 = 0.0f, b1 = 0.0f;
                if (bias) { b0 = bias[col]; b1 = bias[col + 1]; }
                *(float2*)(C + (long)row * ldc + col) =
                    make_float2(acc[mt][nt][0] + b0, acc[mt][nt][1] + b1);
                *(float2*)(C + (long)(row + 8) * ldc + col) =
                    make_float2(acc[mt][nt][2] + b0, acc[mt][nt][3] + b1);
            }
        }
    } else {
        #pragma unroll
        for (int mt = 0; mt < MT; mt++) {
            const int row = m0 + wm * WTM + mt * 16 + g;
            const int b = row >> 10, n = row & 1023;
            #pragma unroll
            for (int nt = 0; nt < NTt; nt++) {
                const int col = n0 + wn * WTN + nt * 8 + c4 * 2;
                const int s = col / PC, r2 = col % PC;
                const int h = r2 >> 6, d = r2 & 63;
                __half* dstb = (s == 0) ? qp : (s == 1) ? kp : vp;
                const float sc = (s == 0) ? PSCALE : 1.0f;
                const long base = (((long)(b * PH + h) << 10) + n) * PD + d;
                *(__half2*)(dstb + base) = __floats2half2_rn(acc[mt][nt][0] * sc, acc[mt][nt][1] * sc);
                *(__half2*)(dstb + base + 8L * PD) = __floats2half2_rn(acc[mt][nt][2] * sc, acc[mt][nt][3] * sc);
            }
        }
    }
}

// ---------------- Stage 1: QK + pre-mix + exp + row sums (unchanged from R10) ----------------
#define S1_K0 55296
#define S1_E  165888
#define S1_SM 190464

__global__ void __launch_bounds__(256)
qk_exp(const __half* __restrict__ qh, const __half* __restrict__ kh,
       __half* __restrict__ eG, float* __restrict__ rsG,
       const float* __restrict__ W_l, const float* __restrict__ b_l)
{
    extern __shared__ char dyn[];
    __half* qT = (__half*)dyn;
    __half* kB[2] = { (__half*)(dyn + S1_K0), (__half*)(dyn + 2 * S1_K0) };
    __half* eS = (__half*)(dyn + S1_E);
    __shared__ float wl[144], bls[12];
    __shared__ float rs[12][32];

    const int tid = threadIdx.x, warp = tid >> 5, lane = tid & 31;
    const int c4 = lane & 3, r8 = lane >> 2;
    const int wA = warp & 3, wN = warp >> 2;
    const int n0 = blockIdx.x * 32, b = blockIdx.y;

    if (tid < 144) wl[tid] = W_l[tid];
    if (tid < 12)  bls[tid] = b_l[tid];
    for (int t = tid; t < 384; t += 256) ((float*)rs)[t] = 0.0f;

    #pragma unroll
    for (int it = 0; it < 12; it++) {
        int c = it * 256 + tid, h = c >> 8, rr = (c >> 3) & 31, cc = (c & 7) * 8;
        cp_async16(smem_u32(qT + (h * 32 + rr) * 72 + cc),
                   qh + (((long)(b * PH + h) << 10) + n0 + rr) * PD + cc);
    }
    cp_commit();

    auto loadk = [&](int mt, __half* buf) {
        #pragma unroll
        for (int it = 0; it < 12; it++) {
            int c = it * 256 + tid, h = c >> 8, rr = (c >> 3) & 31, cc = (c & 7) * 8;
            cp_async16(smem_u32(buf + (h * 32 + rr) * 72 + cc),
                       kh + (((long)(b * PH + h) << 10) + mt * 32 + rr) * PD + cc);
        }
    };
    loadk(0, kB[0]); cp_commit();

    float ps[12][2];
    #pragma unroll
    for (int g = 0; g < 12; g++) { ps[g][0] = 0.0f; ps[g][1] = 0.0f; }

    for (int mt = 0; mt < 32; mt++) {
        __half* cur = kB[mt & 1];
        if (mt + 1 < 32) { loadk(mt + 1, kB[(mt + 1) & 1]); cp_commit(); cp_wait<1>(); }
        else             { cp_wait<0>(); }
        __syncthreads();

        float acc[12][4];
        #pragma unroll
        for (int h = 0; h < 12; h++)
            #pragma unroll
            for (int r = 0; r < 4; r++) acc[h][r] = 0.0f;
        #pragma unroll
        for (int h = 0; h < 12; h++) {
            #pragma unroll
            for (int kc = 0; kc < 4; kc++) {
                uint32_t a0, a1, a2, a3, b0, b1;
                ldmx4(a0, a1, a2, a3,
                      smem_u32(qT + (h * 32 + wN * 16 + (lane & 15)) * 72 + kc * 16 + ((lane >> 4) << 3)));
                ldmx2(b0, b1,
                      smem_u32(cur + (h * 32 + wA * 8 + (lane & 7)) * 72 + kc * 16 + (((lane >> 3) & 1) << 3)));
                mma_f16(acc[h][0], acc[h][1], acc[h][2], acc[h][3], a0, a1, a2, a3, b0, b1);
            }
        }
        #pragma unroll
        for (int g = 0; g < 12; g++) {
            float t0 = bls[g], t1 = t0, t2 = t0, t3 = t0;
            #pragma unroll
            for (int h = 0; h < 12; h++) {
                const float w = wl[g * 12 + h];
                t0 = fmaf(w, acc[h][0], t0); t1 = fmaf(w, acc[h][1], t1);
                t2 = fmaf(w, acc[h][2], t2); t3 = fmaf(w, acc[h][3], t3);
            }
            const float e0 = fexp(t0), e1 = fexp(t1), e2 = fexp(t2), e3 = fexp(t3);
            ps[g][0] += e0 + e1; ps[g][1] += e2 + e3;
            const int mcol = wA * 8 + c4 * 2;
            *(__half2*)(eS + (g * 32 + wN * 16 + r8) * 32 + mcol)     = __floats2half2_rn(e0, e1);
            *(__half2*)(eS + (g * 32 + wN * 16 + r8 + 8) * 32 + mcol) = __floats2half2_rn(e2, e3);
        }
        __syncthreads();
        #pragma unroll
        for (int j = 0; j < 6; j++) {
            int c = tid + j * 256, h = c >> 7, nn = (c >> 2) & 31, q4 = c & 3;
            float4 v = *(float4*)(eS + (h * 32 + nn) * 32 + q4 * 8);
            *(float4*)(eG + ((long)(b * PH + h) << 20) + ((long)(n0 + nn) << 10) + mt * 32 + q4 * 8) = v;
        }
    }
    #pragma unroll
    for (int g = 0; g < 12; g++)
        #pragma unroll
        for (int q = 0; q < 2; q++) {
            ps[g][q] += __shfl_xor_sync(0xFFFFFFFFu, ps[g][q], 1);
            ps[g][q] += __shfl_xor_sync(0xFFFFFFFFu, ps[g][q], 2);
        }
    __syncthreads();
    if (c4 == 0) {
        #pragma unroll
        for (int g = 0; g < 12; g++) {
            atomicAdd(&rs[g][wN * 16 + r8],     ps[g][0]);
            atomicAdd(&rs[g][wN * 16 + r8 + 8], ps[g][1]);
        }
    }
    __syncthreads();
    for (int t = tid; t < 384; t += 256) {
        int h = t >> 5, nn = t & 31;
        rsG[((long)(b * PH + h) << 10) + n0 + nn] = rs[h][nn];
    }
}

// ---------------- Stage 2: normalize + post-mix + attnscale + PV (32-row tiles) ----------------
// smem: eB double [12][32][40], aS [12][32][40], vB double [12][32][72]
#define S2_EB  30720
#define S2_AS  61440
#define S2_V0  92160
#define S2_VST 55296
#define S2_SM  202752

__global__ void __launch_bounds__(256)
mix_pv(const __half* __restrict__ eG, const __half* __restrict__ vh,
       const float* __restrict__ rsG, __half* __restrict__ oh,
       const float* __restrict__ W_w, const float* __restrict__ b_w,
       const float* __restrict__ lamb)
{
    extern __shared__ char dyn[];
    __half* eB[2] = { (__half*)dyn, (__half*)(dyn + S2_EB) };
    __half* aS   = (__half*)(dyn + S2_AS);
    __half* vB[2] = { (__half*)(dyn + S2_V0), (__half*)(dyn + S2_V0 + S2_VST) };
    __shared__ float wp[144], cg[12], invS[12][32];

    const int tid = threadIdx.x, w = tid >> 5, lane = tid & 31;
    const int c4 = lane & 3, r8 = lane >> 2;
    const int n0 = blockIdx.x * 32, b = blockIdx.y;

    if (tid < 144) wp[tid] = W_w[tid] * (1.0f + lamb[tid / 12]);
    if (tid < 12) { const float ad = 1.0f / 1024.0f; cg[tid] = ad + (b_w[tid] - ad) * (1.0f + lamb[tid]); }
    for (int t = tid; t < 384; t += 256) {
        int h = t >> 5, nn = t & 31;
        invS[h][nn] = 1.0f / rsG[((long)(b * PH + h) << 10) + n0 + nn];
    }

    auto loadE = [&](int mt, __half* buf) {
        #pragma unroll
        for (int j = 0; j < 6; j++) {
            int c = tid + j * 256, h = c >> 7, nn = (c >> 2) & 31, q4 = c & 3;
            cp_async16(smem_u32(buf + (h * 32 + nn) * 40 + q4 * 8),
                       eG + ((long)(b * PH + h) << 20) + ((long)(n0 + nn) << 10) + mt * 32 + q4 * 8);
        }
    };
    auto loadV = [&](int mt, __half* buf) {
        #pragma unroll
        for (int it = 0; it < 12; it++) {
            int c = it * 256 + tid, h = c >> 8, rr = (c >> 3) & 31, cc = (c & 7) * 8;
            cp_async16(smem_u32(buf + (h * 32 + rr) * 72 + cc),
                       vh + (((long)(b * PH + h) << 10) + mt * 32 + rr) * PD + cc);
        }
    };

    float acc[12][2][4];
    #pragma unroll
    for (int h = 0; h < 12; h++)
        #pragma unroll
        for (int f = 0; f < 2; f++)
            #pragma unroll
            for (int r = 0; r < 4; r++) acc[h][f][r] = 0.0f;

    loadE(0, eB[0]); loadV(0, vB[0]); cp_commit();

    for (int mt = 0; mt < 32; mt++) {
        __half* ec = eB[mt & 1];
        __half* vc = vB[mt & 1];
        if (mt + 1 < 32) { loadE(mt + 1, eB[(mt + 1) & 1]); loadV(mt + 1, vB[(mt + 1) & 1]); cp_commit(); cp_wait<1>(); }
        else             { cp_wait<0>(); }
        __syncthreads();   // data ready; also guards aS/buffers vs previous iter's mma

        // mix: 1024 elems as 512 half2-pairs; thread p -> (nn = p>>4, m = (p&15)*2)
        #pragma unroll
        for (int p2 = 0; p2 < 2; p2++) {
            const int p = tid + p2 * 256;
            const int nn = p >> 4, m2 = (p & 15) * 2;
            float2 f[12];
            #pragma unroll
            for (int h = 0; h < 12; h++) {
                float2 e2 = __half22float2(*(const __half2*)(ec + (h * 32 + nn) * 40 + m2));
                const float iv = invS[h][nn];
                f[h] = make_float2(e2.x * iv, e2.y * iv);
            }
            #pragma unroll
            for (int g = 0; g < 12; g++) {
                float a0 = cg[g], a1 = cg[g];
                #pragma unroll
                for (int h = 0; h < 12; h++) {
                    const float ww = wp[g * 12 + h];
                    a0 = fmaf(ww, f[h].x, a0);
                    a1 = fmaf(ww, f[h].y, a1);
                }
                *(__half2*)(aS + (g * 32 + nn) * 40 + m2) = __floats2half2_rn(a0, a1);
            }
        }
        __syncthreads();   // aS ready

        #pragma unroll
        for (int h = 0; h < 12; h++) {
            #pragma unroll
            for (int kc = 0; kc < 2; kc++) {
                uint32_t b0, b1;
                ldmx2t(b0, b1, smem_u32(vc + (h * 32 + kc * 16 + (lane & 15)) * 72 + w * 8));
                #pragma unroll
                for (int f = 0; f < 2; f++) {
                    uint32_t a0, a1, a2, a3;
                    ldmx4(a0, a1, a2, a3,
                          smem_u32(aS + (h * 32 + f * 16 + (lane & 15)) * 40 + kc * 16 + ((lane >> 4) << 3)));
                    mma_f16(acc[h][f][0], acc[h][f][1], acc[h][f][2], acc[h][f][3],
                            a0, a1, a2, a3, b0, b1);
                }
            }
        }
        __syncthreads();   // mma reads done before next iter's writes
    }

    #pragma unroll
    for (int h = 0; h < 12; h++)
        #pragma unroll
        for (int f = 0; f < 2; f++) {
            const long base = ((long)((b << 10) + n0 + f * 16 + r8)) * PC + h * 64 + w * 8 + c4 * 2;
            *(__half2*)(oh + base)           = __floats2half2_rn(acc[h][f][0], acc[h][f][1]);
            *(__half2*)(oh + base + 8L * PC) = __floats2half2_rn(acc[h][f][2], acc[h][f][3]);
        }
}

// ---------------- launcher ----------------
extern "C" void kernel_launch(void* const* d_in, const int* in_sizes, int n_in,
                              void* d_out, int out_size)
{
    const float* x      = (const float*)d_in[0];
    const float* W_qkv  = (const float*)d_in[1];
    const float* W_proj = (const float*)d_in[2];
    const float* b_proj = (const float*)d_in[3];
    const float* W_l    = (const float*)d_in[4];
    const float* b_l    = (const float*)d_in[5];
    const float* W_w    = (const float*)d_in[6];
    const float* b_w    = (const float*)d_in[7];
    const float* lamb   = (const float*)d_in[8];
    float* out = (float*)d_out;

    __half *xh, *wqh, *wph, *qh, *kh, *vh, *e, *oh;
    float *rs;
    cudaGetSymbolAddress((void**)&xh,  g_xh);
    cudaGetSymbolAddress((void**)&wqh, g_wqh);
    cudaGetSymbolAddress((void**)&wph, g_wph);
    cudaGetSymbolAddress((void**)&qh,  g_qh);
    cudaGetSymbolAddress((void**)&kh,  g_kh);
    cudaGetSymbolAddress((void**)&vh,  g_vh);
    cudaGetSymbolAddress((void**)&e,   g_e);
    cudaGetSymbolAddress((void**)&rs,  g_rs);
    cudaGetSymbolAddress((void**)&oh,  g_oh);

    const int M = PB * PN;
    constexpr int SM_G = 3 * 2 * 128 * 72 * 2;   // 110592 (BK=64, 3 stages)

    {   const int total = N4_X + N4_WQ + N4_WP;
        f2h_all<<<(total + 255) / 256, 256>>>(x, W_qkv, W_proj, xh, wqh, wph);
    }
    {   auto kfn = gemm_h<128, 128, 64, 3, 2>;
        cudaFuncSetAttribute(kfn, cudaFuncAttributeMaxDynamicSharedMemorySize, SM_G);
        dim3 grid(3 * PC / 128, M / 128, 1);
        kfn<<<grid, 256, SM_G>>>(xh, wqh, nullptr, nullptr, M, 3 * PC, PC, 0, qh, kh, vh);
    }
    {   cudaFuncSetAttribute(qk_exp, cudaFuncAttributeMaxDynamicSharedMemorySize, S1_SM);
        dim3 grid(PN / 32, PB, 1);
        qk_exp<<<grid, 256, S1_SM>>>(qh, kh, e, rs, W_l, b_l);
    }
    {   cudaFuncSetAttribute(mix_pv, cudaFuncAttributeMaxDynamicSharedMemorySize, S2_SM);
        dim3 grid(PN / 32, PB, 1);
        mix_pv<<<grid, 256, S2_SM>>>(e, vh, rs, oh, W_w, b_w, lamb);
    }
    {   auto kfn = gemm_h<128, 128, 64, 3, 0>;
        cudaFuncSetAttribute(kfn, cudaFuncAttributeMaxDynamicSharedMemorySize, SM_G);
        dim3 grid(PC / 128, M / 128, 1);
        kfn<<<grid, 256, SM_G>>>(oh, wph, out, b_proj, M, PC, PC, PC, nullptr, nullptr, nullptr);
    }
}